// round 4
// baseline (speedup 1.0000x reference)
#include <cuda_runtime.h>
#include <math.h>

#define CH 256
#define IC 128
#define BATCH 8
#define NTOK 4096

// Scratch: TH, PH, G each [B][N][IC], n-major rows of 128 floats.
__device__ float g_qkv[3ull * BATCH * NTOK * IC];

// ---------------------------------------------------------------------------
// Kernel 1: projections. rows 0-127 = theta, 128-255 = phi, 256-383 = g.
// Grid (N/32, B), 256 threads. Thread (tx in 8, ty in 32) computes
// 12 rows (r = ty + 32m) x 4 n-cols (n = n0 + 4tx + j).
// ---------------------------------------------------------------------------
__global__ void proj_kernel(const float* __restrict__ x,
                            const float* __restrict__ th_w, const float* __restrict__ th_b,
                            const float* __restrict__ ph_w, const float* __restrict__ ph_b,
                            const float* __restrict__ g_w,  const float* __restrict__ g_b)
{
    extern __shared__ float sm1[];
    float* Xs = sm1;              // [256][32]
    float* Ws = sm1 + 256 * 32;   // [384][36]  (pad 36 -> conflict-free reads)

    const int b   = blockIdx.y;
    const int n0  = blockIdx.x * 32;
    const int tid = threadIdx.x;
    const int tx  = tid & 7;
    const int ty  = tid >> 3;

    // Load x tile [256 c][32 n] (coalesced float4)
    const float* xb = x + (size_t)b * CH * NTOK;
    #pragma unroll
    for (int j = 0; j < 8; j++) {
        int fl = tid + 256 * j;      // 0..2047 float4s
        int c = fl >> 3, u = fl & 7;
        float4 v = *(const float4*)(xb + (size_t)c * NTOK + n0 + 4 * u);
        *(float4*)(Xs + c * 32 + 4 * u) = v;
    }

    float acc[12][4];
    #pragma unroll
    for (int m = 0; m < 12; m++) {
        int r = ty + 32 * m;
        float bias = (r < 128) ? th_b[r] : (r < 256 ? ph_b[r - 128] : g_b[r - 256]);
        acc[m][0] = acc[m][1] = acc[m][2] = acc[m][3] = bias;
    }

    for (int c0 = 0; c0 < 256; c0 += 32) {
        __syncthreads();  // Xs ready (1st iter) / Ws free (later iters)
        // Stage weight chunk Ws[r][c-c0]
        #pragma unroll
        for (int j = 0; j < 12; j++) {
            int fl = tid + 256 * j;    // 0..3071 float4s
            int r = fl >> 3, u = fl & 7;
            const float* wsrc = (r < 128) ? (th_w + (size_t)r * CH)
                              : (r < 256) ? (ph_w + (size_t)(r - 128) * CH)
                                          : (g_w  + (size_t)(r - 256) * CH);
            float4 v = *(const float4*)(wsrc + c0 + 4 * u);
            *(float4*)(Ws + r * 36 + 4 * u) = v;
        }
        __syncthreads();
        #pragma unroll 8
        for (int c = 0; c < 32; c++) {
            float4 xv = *(const float4*)(Xs + (c0 + c) * 32 + 4 * tx);
            #pragma unroll
            for (int m = 0; m < 12; m++) {
                float w = Ws[(ty + 32 * m) * 36 + c];
                acc[m][0] += w * xv.x;
                acc[m][1] += w * xv.y;
                acc[m][2] += w * xv.z;
                acc[m][3] += w * xv.w;
            }
        }
    }

    // Store to [tensor][b][n][r] scratch
    #pragma unroll
    for (int m = 0; m < 12; m++) {
        int r = ty + 32 * m;
        int t = r >> 7;
        int rr = r & 127;
        float* dst = g_qkv + ((size_t)(t * BATCH + b) * NTOK) * IC;
        #pragma unroll
        for (int j = 0; j < 4; j++) {
            int n = n0 + 4 * tx + j;
            dst[(size_t)n * IC + rr] = acc[m][j];
        }
    }
}

// ---------------------------------------------------------------------------
// Kernel 2: flash attention (no scale, full softmax over k) + fused output
// projection + bias + residual.
// Grid (N/64, B), 256 threads as (tx in 16, ty in 16).
// Phase A smem: Qs[128][68], Ks[128][68], Vs[64][132], Ps[64][68]
// Phase B smem (aliased): Os[128][68], Ws[64][260]
// ---------------------------------------------------------------------------
__global__ void attn_kernel(const float* __restrict__ x,
                            const float* __restrict__ Ww,
                            const float* __restrict__ Wb,
                            float* __restrict__ out)
{
    extern __shared__ float sm2[];
    float* Qs = sm2;                       // [128][68]  i-major: Qs[i][q]
    float* Ks = sm2 + 128 * 68;            // [128][68]  i-major: Ks[i][k]
    float* Vs = Ks + 128 * 68;             // [64][132]  k-major: Vs[k][i]
    float* Ps = Vs + 64 * 132;             // [64][68]   k-major: Ps[k][q]
    float* Os = sm2;                       // alias Qs: [128][68] Os[i][q]
    float* Ws = sm2 + 128 * 68;            // alias Ks/Vs: [64][260] Ws[il][c]

    const int b   = blockIdx.y;
    const int q0  = blockIdx.x * 64;
    const int tid = threadIdx.x;
    const int tx  = tid & 15;
    const int ty  = tid >> 4;

    const float* TH = g_qkv + (size_t)b * NTOK * IC;
    const float* PH = g_qkv + (size_t)(BATCH + b) * NTOK * IC;
    const float* GX = g_qkv + (size_t)(2 * BATCH + b) * NTOK * IC;

    // ---- load Q tile (transpose to i-major) ----
    {
        int kk = tid >> 2, ic4 = tid & 3;
        #pragma unroll
        for (int j = 0; j < 8; j++) {
            int i0 = (ic4 + 4 * j) * 4;
            float4 v = *(const float4*)(TH + (size_t)(q0 + kk) * IC + i0);
            Qs[(i0 + 0) * 68 + kk] = v.x;
            Qs[(i0 + 1) * 68 + kk] = v.y;
            Qs[(i0 + 2) * 68 + kk] = v.z;
            Qs[(i0 + 3) * 68 + kk] = v.w;
        }
    }

    float mrow[4], lrow[4], O[4][8];
    #pragma unroll
    for (int r = 0; r < 4; r++) {
        mrow[r] = -INFINITY; lrow[r] = 0.f;
        #pragma unroll
        for (int c = 0; c < 8; c++) O[r][c] = 0.f;
    }

    for (int kt = 0; kt < NTOK / 64; kt++) {
        int k0 = kt * 64;
        // ---- load K (transposed) and V (direct) tiles ----
        {
            int kk = tid >> 2, ic4 = tid & 3;
            #pragma unroll
            for (int j = 0; j < 8; j++) {
                int i0 = (ic4 + 4 * j) * 4;
                float4 v = *(const float4*)(PH + (size_t)(k0 + kk) * IC + i0);
                Ks[(i0 + 0) * 68 + kk] = v.x;
                Ks[(i0 + 1) * 68 + kk] = v.y;
                Ks[(i0 + 2) * 68 + kk] = v.z;
                Ks[(i0 + 3) * 68 + kk] = v.w;
                float4 g = *(const float4*)(GX + (size_t)(k0 + kk) * IC + i0);
                *(float4*)(Vs + kk * 132 + i0) = g;
            }
        }
        __syncthreads();

        // ---- S = Q K^T for this tile: thread owns q=4ty+r, k=tx+16c ----
        float S[4][4] = {};
        #pragma unroll 4
        for (int i = 0; i < 128; i++) {
            float4 qv = *(const float4*)(Qs + i * 68 + 4 * ty);
            #pragma unroll
            for (int c = 0; c < 4; c++) {
                float kv = Ks[i * 68 + tx + 16 * c];
                S[0][c] += qv.x * kv;
                S[1][c] += qv.y * kv;
                S[2][c] += qv.z * kv;
                S[3][c] += qv.w * kv;
            }
        }

        // ---- online softmax (row reductions across the 16 tx lanes) ----
        #pragma unroll
        for (int r = 0; r < 4; r++) {
            float mx = fmaxf(fmaxf(S[r][0], S[r][1]), fmaxf(S[r][2], S[r][3]));
            #pragma unroll
            for (int o = 8; o > 0; o >>= 1)
                mx = fmaxf(mx, __shfl_xor_sync(0xffffffffu, mx, o));
            float mn  = fmaxf(mrow[r], mx);
            float esc = __expf(mrow[r] - mn);
            float s = 0.f;
            #pragma unroll
            for (int c = 0; c < 4; c++) {
                S[r][c] = __expf(S[r][c] - mn);
                s += S[r][c];
            }
            #pragma unroll
            for (int o = 8; o > 0; o >>= 1)
                s += __shfl_xor_sync(0xffffffffu, s, o);
            lrow[r] = lrow[r] * esc + s;
            mrow[r] = mn;
            #pragma unroll
            for (int c = 0; c < 8; c++) O[r][c] *= esc;
            #pragma unroll
            for (int c = 0; c < 4; c++)
                Ps[(tx + 16 * c) * 68 + 4 * ty + r] = S[r][c];
        }
        __syncthreads();

        // ---- O += P V : thread owns q=4ty+r, i=tx+16c' ----
        #pragma unroll 2
        for (int k = 0; k < 64; k++) {
            float4 pv = *(const float4*)(Ps + k * 68 + 4 * ty);
            #pragma unroll
            for (int c = 0; c < 8; c++) {
                float vv = Vs[k * 132 + tx + 16 * c];
                O[0][c] += pv.x * vv;
                O[1][c] += pv.y * vv;
                O[2][c] += pv.z * vv;
                O[3][c] += pv.w * vv;
            }
        }
        __syncthreads();
    }

    // ---- normalize, park O in smem as Os[i][q] (aliases Qs; safe: synced) ----
    #pragma unroll
    for (int r = 0; r < 4; r++) {
        float inv = 1.f / lrow[r];
        #pragma unroll
        for (int c = 0; c < 8; c++)
            Os[(tx + 16 * c) * 68 + 4 * ty + r] = O[r][c] * inv;
    }
    __syncthreads();

    // ---- fused output projection: out[c][q] = sum_i Ww[c][i] * Os[i][q] ----
    float acc[16][4];
    #pragma unroll
    for (int cc = 0; cc < 16; cc++)
        acc[cc][0] = acc[cc][1] = acc[cc][2] = acc[cc][3] = 0.f;

    for (int ci = 0; ci < 2; ci++) {
        // stage Ww chunk transposed: Ws[il][c] = Ww[c][ci*64 + il]
        #pragma unroll
        for (int j = 0; j < 16; j++) {
            int fl = tid + 256 * j;     // 0..4095 float4s
            int c = fl >> 4, u = fl & 15;
            float4 v = *(const float4*)(Ww + (size_t)c * IC + ci * 64 + 4 * u);
            Ws[(4 * u + 0) * 260 + c] = v.x;
            Ws[(4 * u + 1) * 260 + c] = v.y;
            Ws[(4 * u + 2) * 260 + c] = v.z;
            Ws[(4 * u + 3) * 260 + c] = v.w;
        }
        __syncthreads();
        #pragma unroll 4
        for (int il = 0; il < 64; il++) {
            int i = ci * 64 + il;
            float4 ov = *(const float4*)(Os + i * 68 + 4 * tx);
            #pragma unroll
            for (int cc = 0; cc < 16; cc++) {
                float w = Ws[il * 260 + ty + 16 * cc];
                acc[cc][0] += w * ov.x;
                acc[cc][1] += w * ov.y;
                acc[cc][2] += w * ov.z;
                acc[cc][3] += w * ov.w;
            }
        }
        __syncthreads();
    }

    // ---- write: + W_b + residual x ----
    #pragma unroll
    for (int cc = 0; cc < 16; cc++) {
        int c = ty + 16 * cc;
        float wb = Wb[c];
        size_t base = ((size_t)b * CH + c) * NTOK + q0 + 4 * tx;
        float4 xr = *(const float4*)(x + base);
        float4 o;
        o.x = acc[cc][0] + wb + xr.x;
        o.y = acc[cc][1] + wb + xr.y;
        o.z = acc[cc][2] + wb + xr.z;
        o.w = acc[cc][3] + wb + xr.w;
        *(float4*)(out + base) = o;
    }
}

// ---------------------------------------------------------------------------
extern "C" void kernel_launch(void* const* d_in, const int* in_sizes, int n_in,
                              void* d_out, int out_size)
{
    const float* x    = (const float*)d_in[0];
    const float* g_w  = (const float*)d_in[1];
    const float* g_b  = (const float*)d_in[2];
    const float* th_w = (const float*)d_in[3];
    const float* th_b = (const float*)d_in[4];
    const float* ph_w = (const float*)d_in[5];
    const float* ph_b = (const float*)d_in[6];
    const float* W_w  = (const float*)d_in[7];
    const float* W_b  = (const float*)d_in[8];
    float* out = (float*)d_out;

    const int SMEM1 = (256 * 32 + 384 * 36) * 4;                    // 88064 B
    const int SMEM2 = (128 * 68 + 128 * 68 + 64 * 132 + 64 * 68) * 4; // 120832 B
    cudaFuncSetAttribute(proj_kernel, cudaFuncAttributeMaxDynamicSharedMemorySize, SMEM1);
    cudaFuncSetAttribute(attn_kernel, cudaFuncAttributeMaxDynamicSharedMemorySize, SMEM2);

    proj_kernel<<<dim3(NTOK / 32, BATCH), 256, SMEM1>>>(
        x, th_w, th_b, ph_w, ph_b, g_w, g_b);
    attn_kernel<<<dim3(NTOK / 64, BATCH), 256, SMEM2>>>(
        x, W_w, W_b, out);
}

// round 11
// speedup vs baseline: 2.6789x; 2.6789x over previous
#include <cuda_runtime.h>
#include <cuda_bf16.h>
#include <cstdint>
#include <math.h>

#define CH 256
#define IC 128
#define BATCH 8
#define NTOK 4096

// bf16 hi/lo planes. th/ph: [b][n][ic]; g: [b][ic][n].
__device__ __align__(16) __nv_bfloat16 g_th_hi[(size_t)BATCH * NTOK * IC];
__device__ __align__(16) __nv_bfloat16 g_th_lo[(size_t)BATCH * NTOK * IC];
__device__ __align__(16) __nv_bfloat16 g_ph_hi[(size_t)BATCH * NTOK * IC];
__device__ __align__(16) __nv_bfloat16 g_ph_lo[(size_t)BATCH * NTOK * IC];
__device__ __align__(16) __nv_bfloat16 g_g_hi[(size_t)BATCH * NTOK * IC];
__device__ __align__(16) __nv_bfloat16 g_g_lo[(size_t)BATCH * NTOK * IC];

#define CVT2(r, a, b) asm("cvt.rn.satfinite.bf16x2.f32 %0, %1, %2;" : "=r"(r) : "f"(b), "f"(a))

__device__ __forceinline__ void mma_bf16(float d[4], uint32_t a0, uint32_t a1,
                                         uint32_t a2, uint32_t a3,
                                         uint32_t b0, uint32_t b1) {
    asm volatile(
        "mma.sync.aligned.m16n8k16.row.col.f32.bf16.bf16.f32 "
        "{%0,%1,%2,%3},{%4,%5,%6,%7},{%8,%9},{%0,%1,%2,%3};"
        : "+f"(d[0]), "+f"(d[1]), "+f"(d[2]), "+f"(d[3])
        : "r"(a0), "r"(a1), "r"(a2), "r"(a3), "r"(b0), "r"(b1));
}

// exp(x) on the FMA pipe (no MUFU): 2^(x*log2e), round trick + deg-5 poly.
__device__ __forceinline__ float fexp(float x) {
    float y = x * 1.44269504089f;
    float z = y + 12582912.0f;               // 1.5*2^23
    int n = __float_as_int(z) - 0x4B400000;
    float f = y - (z - 12582912.0f);         // f in [-0.5, 0.5]
    float p = 1.33336e-3f;
    p = fmaf(p, f, 9.61813e-3f);
    p = fmaf(p, f, 5.550411e-2f);
    p = fmaf(p, f, 2.4022651e-1f);
    p = fmaf(p, f, 6.9314718e-1f);
    p = fmaf(p, f, 1.0f);
    return __int_as_float(__float_as_int(p) + (n << 23));
}

// ---------------------------------------------------------------------------
// Kernel 1: fp32 projections -> bf16 hi/lo planes (smem transpose for stores)
// ---------------------------------------------------------------------------
__global__ void proj_kernel(const float* __restrict__ x,
                            const float* __restrict__ th_w, const float* __restrict__ th_b,
                            const float* __restrict__ ph_w, const float* __restrict__ ph_b,
                            const float* __restrict__ g_w,  const float* __restrict__ g_b)
{
    extern __shared__ float sm1[];
    float* Xs = sm1;              // [256][32]
    float* Ws = sm1 + 8192;       // [384][36]
    const int b = blockIdx.y, n0 = blockIdx.x * 32, tid = threadIdx.x;
    const int tx = tid & 7, ty = tid >> 3;

    const float* xb = x + (size_t)b * CH * NTOK;
    #pragma unroll
    for (int j = 0; j < 8; j++) {
        int fl = tid + 256 * j, c = fl >> 3, u = fl & 7;
        *(float4*)(Xs + c * 32 + 4 * u) = *(const float4*)(xb + (size_t)c * NTOK + n0 + 4 * u);
    }
    float acc[12][4];
    #pragma unroll
    for (int m = 0; m < 12; m++) {
        int r = ty + 32 * m;
        float bias = (r < 128) ? th_b[r] : (r < 256 ? ph_b[r - 128] : g_b[r - 256]);
        acc[m][0] = acc[m][1] = acc[m][2] = acc[m][3] = bias;
    }
    for (int c0 = 0; c0 < 256; c0 += 32) {
        __syncthreads();
        #pragma unroll
        for (int j = 0; j < 12; j++) {
            int fl = tid + 256 * j, r = fl >> 3, u = fl & 7;
            const float* ws = (r < 128) ? (th_w + (size_t)r * CH)
                            : (r < 256) ? (ph_w + (size_t)(r - 128) * CH)
                                        : (g_w + (size_t)(r - 256) * CH);
            *(float4*)(Ws + r * 36 + 4 * u) = *(const float4*)(ws + c0 + 4 * u);
        }
        __syncthreads();
        #pragma unroll 8
        for (int c = 0; c < 32; c++) {
            float4 xv = *(const float4*)(Xs + (c0 + c) * 32 + 4 * tx);
            #pragma unroll
            for (int m = 0; m < 12; m++) {
                float w = Ws[(ty + 32 * m) * 36 + c];
                acc[m][0] += w * xv.x; acc[m][1] += w * xv.y;
                acc[m][2] += w * xv.z; acc[m][3] += w * xv.w;
            }
        }
    }
    __syncthreads();
    float* Sm = sm1;   // [384][33]
    #pragma unroll
    for (int m = 0; m < 12; m++) {
        int r = ty + 32 * m;
        #pragma unroll
        for (int j = 0; j < 4; j++) Sm[r * 33 + 4 * tx + j] = acc[m][j];
    }
    __syncthreads();
    const size_t bN = (size_t)b * NTOK;
    #pragma unroll
    for (int it = 0; it < 4; it++) {   // theta/phi: [n][ic] rows
        int idx = tid + 256 * it;
        int t = idx >> 9, rem = idx & 511, n = rem >> 4, seg = rem & 15;
        uint32_t hp[4], lp[4];
        #pragma unroll
        for (int j = 0; j < 4; j++) {
            float a = Sm[(t * 128 + seg * 8 + 2 * j) * 33 + n];
            float c = Sm[(t * 128 + seg * 8 + 2 * j + 1) * 33 + n];
            __nv_bfloat16 ha = __float2bfloat16(a), hc = __float2bfloat16(c);
            CVT2(hp[j], a, c);
            CVT2(lp[j], a - __bfloat162float(ha), c - __bfloat162float(hc));
        }
        __nv_bfloat16* hi = t ? g_ph_hi : g_th_hi;
        __nv_bfloat16* lo = t ? g_ph_lo : g_th_lo;
        size_t base = (bN + n0 + n) * IC + seg * 8;
        *(uint4*)(hi + base) = make_uint4(hp[0], hp[1], hp[2], hp[3]);
        *(uint4*)(lo + base) = make_uint4(lp[0], lp[1], lp[2], lp[3]);
    }
    #pragma unroll
    for (int it = 0; it < 2; it++) {   // g transposed: [ic][n]
        int idx = tid + 256 * it, ic = idx >> 2, ch = idx & 3;
        uint32_t hp[4], lp[4];
        #pragma unroll
        for (int j = 0; j < 4; j++) {
            float a = Sm[(256 + ic) * 33 + ch * 8 + 2 * j];
            float c = Sm[(256 + ic) * 33 + ch * 8 + 2 * j + 1];
            __nv_bfloat16 ha = __float2bfloat16(a), hc = __float2bfloat16(c);
            CVT2(hp[j], a, c);
            CVT2(lp[j], a - __bfloat162float(ha), c - __bfloat162float(hc));
        }
        size_t base = ((size_t)b * IC + ic) * NTOK + n0 + ch * 8;
        *(uint4*)(g_g_hi + base) = make_uint4(hp[0], hp[1], hp[2], hp[3]);
        *(uint4*)(g_g_lo + base) = make_uint4(lp[0], lp[1], lp[2], lp[3]);
    }
}

// ---------------------------------------------------------------------------
// Kernel 2: mma.sync flash attention + fused fp32 out-proj. 256 thr, grid (32,8)
// smem (bytes): Qhi/Qlo [128][136]b16, Khi/Klo [64][136], Ghi/Glo [128][72],
//               Phi/Plo [128][72]. Phase B: Os f32 [128][132], Wt f32 [128][260].
// red [2][128]f32 lives above both phases.
// ---------------------------------------------------------------------------
#define O_QHI 0
#define O_QLO 34816
#define O_KHI 69632
#define O_KLO 87040
#define O_GHI 104448
#define O_GLO 122880
#define O_PHI 141312
#define O_PLO 159744
#define O_OS 0
#define O_WT 69632
#define O_RED 202752
#define SMEM_ATTN 203776

__global__ void __launch_bounds__(256, 1)
attn_kernel(const float* __restrict__ x, const float* __restrict__ Ww,
            const float* __restrict__ Wb, float* __restrict__ out)
{
    extern __shared__ char smc[];
    const int b = blockIdx.y, q0 = blockIdx.x * 128, tid = threadIdx.x;
    const int lane = tid & 31, wid = tid >> 5;
    const int wq = wid & 3, wk = wid >> 2;
    const int lr = lane >> 2, lc = lane & 3;
    const int qb = 32 * wq, kb = 32 * wk, ib = 64 * wk;
    const size_t bN = (size_t)b * NTOK;
    float* red = (float*)(smc + O_RED);

    // ---- Q tile -> smem (hi/lo), padded rows 272B ----
    #pragma unroll
    for (int j = 0; j < 16; j++) {
        int idx = tid + 256 * j;
        int plane = idx >> 11, e = idx & 2047, row = e >> 4, seg = e & 15;
        const __nv_bfloat16* src = (plane ? g_th_lo : g_th_hi) + (bN + q0 + row) * IC + seg * 8;
        *(uint4*)(smc + (plane ? O_QLO : O_QHI) + row * 272 + seg * 16) = *(const uint4*)src;
    }

    float Ofr[2][8][4] = {};
    float lsum[4] = {0.f, 0.f, 0.f, 0.f};
    float M[4];

    for (int kt = 0; kt < NTOK / 64; kt++) {
        const int k0 = kt * 64;
        __syncthreads();                      // prev tiles consumed (also Q ready @kt0)
        #pragma unroll
        for (int j = 0; j < 8; j++) {         // K tile [64key][136ic]
            int idx = tid + 256 * j;
            int plane = idx >> 10, e = idx & 1023, row = e >> 4, seg = e & 15;
            const __nv_bfloat16* src = (plane ? g_ph_lo : g_ph_hi) + (bN + k0 + row) * IC + seg * 8;
            *(uint4*)(smc + (plane ? O_KLO : O_KHI) + row * 272 + seg * 16) = *(const uint4*)src;
        }
        #pragma unroll
        for (int j = 0; j < 8; j++) {         // G tile [128i][72key]
            int idx = tid + 256 * j;
            int plane = idx >> 10, e = idx & 1023, row = e >> 3, seg = e & 7;
            const __nv_bfloat16* src = (plane ? g_g_lo : g_g_hi) + ((size_t)b * IC + row) * NTOK + k0 + seg * 8;
            *(uint4*)(smc + (plane ? O_GLO : O_GHI) + row * 144 + seg * 16) = *(const uint4*)src;
        }
        __syncthreads();

        // ---- S = Q K^T (warp: 32q x 32key), 3-term bf16 split ----
        float S[2][4][4] = {};
        #pragma unroll
        for (int ks = 0; ks < 8; ks++) {
            uint32_t ah[2][4], al[2][4];
            #pragma unroll
            for (int mt = 0; mt < 2; mt++) {
                int ro = (qb + 16 * mt + lr) * 272 + 32 * ks + 4 * lc;
                ah[mt][0] = *(const uint32_t*)(smc + O_QHI + ro);
                ah[mt][1] = *(const uint32_t*)(smc + O_QHI + ro + 8 * 272);
                ah[mt][2] = *(const uint32_t*)(smc + O_QHI + ro + 16);
                ah[mt][3] = *(const uint32_t*)(smc + O_QHI + ro + 8 * 272 + 16);
                al[mt][0] = *(const uint32_t*)(smc + O_QLO + ro);
                al[mt][1] = *(const uint32_t*)(smc + O_QLO + ro + 8 * 272);
                al[mt][2] = *(const uint32_t*)(smc + O_QLO + ro + 16);
                al[mt][3] = *(const uint32_t*)(smc + O_QLO + ro + 8 * 272 + 16);
            }
            #pragma unroll
            for (int nt = 0; nt < 4; nt++) {
                int ro = (kb + 8 * nt + lr) * 272 + 32 * ks + 4 * lc;
                uint32_t bh0 = *(const uint32_t*)(smc + O_KHI + ro);
                uint32_t bh1 = *(const uint32_t*)(smc + O_KHI + ro + 16);
                uint32_t bl0 = *(const uint32_t*)(smc + O_KLO + ro);
                uint32_t bl1 = *(const uint32_t*)(smc + O_KLO + ro + 16);
                #pragma unroll
                for (int mt = 0; mt < 2; mt++) {
                    mma_bf16(S[mt][nt], ah[mt][0], ah[mt][1], ah[mt][2], ah[mt][3], bh0, bh1);
                    mma_bf16(S[mt][nt], ah[mt][0], ah[mt][1], ah[mt][2], ah[mt][3], bl0, bl1);
                    mma_bf16(S[mt][nt], al[mt][0], al[mt][1], al[mt][2], al[mt][3], bh0, bh1);
                }
            }
        }

        if (kt == 0) {   // fixed reference max from tile 0
            #pragma unroll
            for (int mt = 0; mt < 2; mt++) {
                float m0 = -1e30f, m1 = -1e30f;
                #pragma unroll
                for (int nt = 0; nt < 4; nt++) {
                    m0 = fmaxf(m0, fmaxf(S[mt][nt][0], S[mt][nt][1]));
                    m1 = fmaxf(m1, fmaxf(S[mt][nt][2], S[mt][nt][3]));
                }
                m0 = fmaxf(m0, __shfl_xor_sync(0xffffffffu, m0, 1));
                m0 = fmaxf(m0, __shfl_xor_sync(0xffffffffu, m0, 2));
                m1 = fmaxf(m1, __shfl_xor_sync(0xffffffffu, m1, 1));
                m1 = fmaxf(m1, __shfl_xor_sync(0xffffffffu, m1, 2));
                if (lc == 0) {
                    red[wk * 128 + qb + 16 * mt + lr] = m0;
                    red[wk * 128 + qb + 16 * mt + lr + 8] = m1;
                }
            }
            __syncthreads();
            #pragma unroll
            for (int mt = 0; mt < 2; mt++) {
                M[2 * mt]     = fmaxf(red[qb + 16 * mt + lr],     red[128 + qb + 16 * mt + lr]);
                M[2 * mt + 1] = fmaxf(red[qb + 16 * mt + lr + 8], red[128 + qb + 16 * mt + lr + 8]);
            }
        }

        // ---- P = exp(S - M), bf16 hi/lo -> smem ----
        #pragma unroll
        for (int mt = 0; mt < 2; mt++) {
            int r0 = (qb + 16 * mt + lr) * 144 + kb * 2 + lc * 4;  // byte offset, stride 144
            #pragma unroll
            for (int nt = 0; nt < 4; nt++) {
                float p00 = fexp(S[mt][nt][0] - M[2 * mt]);
                float p01 = fexp(S[mt][nt][1] - M[2 * mt]);
                float p10 = fexp(S[mt][nt][2] - M[2 * mt + 1]);
                float p11 = fexp(S[mt][nt][3] - M[2 * mt + 1]);
                lsum[2 * mt] += p00 + p01;
                lsum[2 * mt + 1] += p10 + p11;
                uint32_t h0, h1, l0, l1;
                __nv_bfloat16 c0 = __float2bfloat16(p00), c1 = __float2bfloat16(p01);
                __nv_bfloat16 c2 = __float2bfloat16(p10), c3 = __float2bfloat16(p11);
                CVT2(h0, p00, p01); CVT2(h1, p10, p11);
                CVT2(l0, p00 - __bfloat162float(c0), p01 - __bfloat162float(c1));
                CVT2(l1, p10 - __bfloat162float(c2), p11 - __bfloat162float(c3));
                *(uint32_t*)(smc + O_PHI + r0 + 16 * nt) = h0;
                *(uint32_t*)(smc + O_PHI + r0 + 16 * nt + 8 * 144) = h1;
                *(uint32_t*)(smc + O_PLO + r0 + 16 * nt) = l0;
                *(uint32_t*)(smc + O_PLO + r0 + 16 * nt + 8 * 144) = l1;
            }
        }
        __syncthreads();

        // ---- O += P G^T (warp: 32q x 64i), 3-term ----
        #pragma unroll
        for (int ks = 0; ks < 4; ks++) {
            uint32_t ph[2][4], pl[2][4];
            #pragma unroll
            for (int mt = 0; mt < 2; mt++) {
                int ro = (qb + 16 * mt + lr) * 144 + 32 * ks + 4 * lc;
                ph[mt][0] = *(const uint32_t*)(smc + O_PHI + ro);
                ph[mt][1] = *(const uint32_t*)(smc + O_PHI + ro + 8 * 144);
                ph[mt][2] = *(const uint32_t*)(smc + O_PHI + ro + 16);
                ph[mt][3] = *(const uint32_t*)(smc + O_PHI + ro + 8 * 144 + 16);
                pl[mt][0] = *(const uint32_t*)(smc + O_PLO + ro);
                pl[mt][1] = *(const uint32_t*)(smc + O_PLO + ro + 8 * 144);
                pl[mt][2] = *(const uint32_t*)(smc + O_PLO + ro + 16);
                pl[mt][3] = *(const uint32_t*)(smc + O_PLO + ro + 8 * 144 + 16);
            }
            #pragma unroll
            for (int nt = 0; nt < 8; nt++) {
                int ro = (ib + 8 * nt + lr) * 144 + 32 * ks + 4 * lc;
                uint32_t gh0 = *(const uint32_t*)(smc + O_GHI + ro);
                uint32_t gh1 = *(const uint32_t*)(smc + O_GHI + ro + 16);
                uint32_t gl0 = *(const uint32_t*)(smc + O_GLO + ro);
                uint32_t gl1 = *(const uint32_t*)(smc + O_GLO + ro + 16);
                #pragma unroll
                for (int mt = 0; mt < 2; mt++) {
                    mma_bf16(Ofr[mt][nt], ph[mt][0], ph[mt][1], ph[mt][2], ph[mt][3], gh0, gh1);
                    mma_bf16(Ofr[mt][nt], ph[mt][0], ph[mt][1], ph[mt][2], ph[mt][3], gl0, gl1);
                    mma_bf16(Ofr[mt][nt], pl[mt][0], pl[mt][1], pl[mt][2], pl[mt][3], gh0, gh1);
                }
            }
        }
    }

    // ---- l reduce, normalize, write Os[i][q] fp32 ----
    #pragma unroll
    for (int v = 0; v < 4; v++) {
        lsum[v] += __shfl_xor_sync(0xffffffffu, lsum[v], 1);
        lsum[v] += __shfl_xor_sync(0xffffffffu, lsum[v], 2);
    }
    if (lc == 0) {
        #pragma unroll
        for (int mt = 0; mt < 2; mt++) {
            red[wk * 128 + qb + 16 * mt + lr] = lsum[2 * mt];
            red[wk * 128 + qb + 16 * mt + lr + 8] = lsum[2 * mt + 1];
        }
    }
    __syncthreads();
    float inv[4];
    #pragma unroll
    for (int mt = 0; mt < 2; mt++) {
        inv[2 * mt]     = 1.f / (red[qb + 16 * mt + lr]     + red[128 + qb + 16 * mt + lr]);
        inv[2 * mt + 1] = 1.f / (red[qb + 16 * mt + lr + 8] + red[128 + qb + 16 * mt + lr + 8]);
    }
    __syncthreads();
    float* Os = (float*)(smc + O_OS);   // [128 i][132], aliases Q (dead)
    #pragma unroll
    for (int mt = 0; mt < 2; mt++)
        #pragma unroll
        for (int nt = 0; nt < 8; nt++)
            #pragma unroll
            for (int j = 0; j < 4; j++) {
                int q = qb + 16 * mt + lr + 8 * (j >> 1);
                int i = ib + 8 * nt + 2 * lc + (j & 1);
                Os[i * 132 + q] = Ofr[mt][nt][j] * inv[2 * mt + (j >> 1)];
            }
    float* Wt = (float*)(smc + O_WT);   // [128 i][260] = Ww^T, aliases K/G/P (dead)
    #pragma unroll
    for (int j = 0; j < 32; j++) {
        int fl = tid + 256 * j, c = fl >> 5, i4 = (fl & 31) * 4;
        float4 v = *(const float4*)(Ww + (size_t)c * IC + i4);
        Wt[(i4 + 0) * 260 + c] = v.x; Wt[(i4 + 1) * 260 + c] = v.y;
        Wt[(i4 + 2) * 260 + c] = v.z; Wt[(i4 + 3) * 260 + c] = v.w;
    }
    __syncthreads();

    // ---- out[c][q] = Ww Os + b + x (fp32 SIMT) ----
    const int tx = tid & 15, ty = tid >> 4;
    for (int qh = 0; qh < 2; qh++) {
        float acc[16][4];
        #pragma unroll
        for (int cc = 0; cc < 16; cc++)
            acc[cc][0] = acc[cc][1] = acc[cc][2] = acc[cc][3] = 0.f;
        #pragma unroll 4
        for (int i = 0; i < 128; i++) {
            float4 ov = *(const float4*)(Os + i * 132 + qh * 64 + 4 * tx);
            #pragma unroll
            for (int cc = 0; cc < 16; cc++) {
                float w = Wt[i * 260 + ty + 16 * cc];
                acc[cc][0] += w * ov.x; acc[cc][1] += w * ov.y;
                acc[cc][2] += w * ov.z; acc[cc][3] += w * ov.w;
            }
        }
        #pragma unroll
        for (int cc = 0; cc < 16; cc++) {
            int c = ty + 16 * cc;
            float wb = Wb[c];
            size_t base = ((size_t)b * CH + c) * NTOK + q0 + qh * 64 + 4 * tx;
            float4 xr = *(const float4*)(x + base);
            float4 o;
            o.x = acc[cc][0] + wb + xr.x; o.y = acc[cc][1] + wb + xr.y;
            o.z = acc[cc][2] + wb + xr.z; o.w = acc[cc][3] + wb + xr.w;
            *(float4*)(out + base) = o;
        }
    }
}

// ---------------------------------------------------------------------------
extern "C" void kernel_launch(void* const* d_in, const int* in_sizes, int n_in,
                              void* d_out, int out_size)
{
    const float* x    = (const float*)d_in[0];
    const float* g_w  = (const float*)d_in[1];
    const float* g_b  = (const float*)d_in[2];
    const float* th_w = (const float*)d_in[3];
    const float* th_b = (const float*)d_in[4];
    const float* ph_w = (const float*)d_in[5];
    const float* ph_b = (const float*)d_in[6];
    const float* W_w  = (const float*)d_in[7];
    const float* W_b  = (const float*)d_in[8];
    float* out = (float*)d_out;

    const int SMEM1 = (256 * 32 + 384 * 36) * 4;
    cudaFuncSetAttribute(proj_kernel, cudaFuncAttributeMaxDynamicSharedMemorySize, SMEM1);
    cudaFuncSetAttribute(attn_kernel, cudaFuncAttributeMaxDynamicSharedMemorySize, SMEM_ATTN);

    proj_kernel<<<dim3(NTOK / 32, BATCH), 256, SMEM1>>>(
        x, th_w, th_b, ph_w, ph_b, g_w, g_b);
    attn_kernel<<<dim3(NTOK / 128, BATCH), 256, SMEM_ATTN>>>(
        x, W_w, W_b, out);
}

// round 12
// speedup vs baseline: 2.9189x; 1.0896x over previous
#include <cuda_runtime.h>
#include <cuda_bf16.h>
#include <cstdint>
#include <math.h>

#define CH 256
#define IC 128
#define BATCH 8
#define NTOK 4096

// bf16 hi/lo planes. th/ph: [b][n][ic]; g: [b][ic][n].
__device__ __align__(16) __nv_bfloat16 g_th_hi[(size_t)BATCH * NTOK * IC];
__device__ __align__(16) __nv_bfloat16 g_th_lo[(size_t)BATCH * NTOK * IC];
__device__ __align__(16) __nv_bfloat16 g_ph_hi[(size_t)BATCH * NTOK * IC];
__device__ __align__(16) __nv_bfloat16 g_ph_lo[(size_t)BATCH * NTOK * IC];
__device__ __align__(16) __nv_bfloat16 g_g_hi[(size_t)BATCH * NTOK * IC];
__device__ __align__(16) __nv_bfloat16 g_g_lo[(size_t)BATCH * NTOK * IC];

#define CVT2(r, a, b) asm("cvt.rn.satfinite.bf16x2.f32 %0, %1, %2;" : "=r"(r) : "f"(b), "f"(a))
#define CP16(d, s) asm volatile("cp.async.cg.shared.global [%0], [%1], 16;" :: "r"(d), "l"(s) : "memory")
#define CP_COMMIT() asm volatile("cp.async.commit_group;" ::: "memory")
#define CP_WAIT(n) asm volatile("cp.async.wait_group %0;" :: "n"(n) : "memory")

__device__ __forceinline__ void mma_bf16(float d[4], uint32_t a0, uint32_t a1,
                                         uint32_t a2, uint32_t a3,
                                         uint32_t b0, uint32_t b1) {
    asm volatile(
        "mma.sync.aligned.m16n8k16.row.col.f32.bf16.bf16.f32 "
        "{%0,%1,%2,%3},{%4,%5,%6,%7},{%8,%9},{%0,%1,%2,%3};"
        : "+f"(d[0]), "+f"(d[1]), "+f"(d[2]), "+f"(d[3])
        : "r"(a0), "r"(a1), "r"(a2), "r"(a3), "r"(b0), "r"(b1));
}

// exp(x) on the FMA pipe (no MUFU): 2^(x*log2e), round trick + deg-5 poly.
__device__ __forceinline__ float fexp(float x) {
    float y = x * 1.44269504089f;
    float z = y + 12582912.0f;               // 1.5*2^23
    int n = __float_as_int(z) - 0x4B400000;
    float f = y - (z - 12582912.0f);         // f in [-0.5, 0.5]
    float p = 1.33336e-3f;
    p = fmaf(p, f, 9.61813e-3f);
    p = fmaf(p, f, 5.550411e-2f);
    p = fmaf(p, f, 2.4022651e-1f);
    p = fmaf(p, f, 6.9314718e-1f);
    p = fmaf(p, f, 1.0f);
    return __int_as_float(__float_as_int(p) + (n << 23));
}

// ---------------------------------------------------------------------------
// Kernel 1: fp32 projections -> bf16 hi/lo planes (smem transpose for stores)
// ---------------------------------------------------------------------------
__global__ void proj_kernel(const float* __restrict__ x,
                            const float* __restrict__ th_w, const float* __restrict__ th_b,
                            const float* __restrict__ ph_w, const float* __restrict__ ph_b,
                            const float* __restrict__ g_w,  const float* __restrict__ g_b)
{
    extern __shared__ float sm1[];
    float* Xs = sm1;              // [256][32]
    float* Ws = sm1 + 8192;       // [384][36]
    const int b = blockIdx.y, n0 = blockIdx.x * 32, tid = threadIdx.x;
    const int tx = tid & 7, ty = tid >> 3;

    const float* xb = x + (size_t)b * CH * NTOK;
    #pragma unroll
    for (int j = 0; j < 8; j++) {
        int fl = tid + 256 * j, c = fl >> 3, u = fl & 7;
        *(float4*)(Xs + c * 32 + 4 * u) = *(const float4*)(xb + (size_t)c * NTOK + n0 + 4 * u);
    }
    float acc[12][4];
    #pragma unroll
    for (int m = 0; m < 12; m++) {
        int r = ty + 32 * m;
        float bias = (r < 128) ? th_b[r] : (r < 256 ? ph_b[r - 128] : g_b[r - 256]);
        acc[m][0] = acc[m][1] = acc[m][2] = acc[m][3] = bias;
    }
    for (int c0 = 0; c0 < 256; c0 += 32) {
        __syncthreads();
        #pragma unroll
        for (int j = 0; j < 12; j++) {
            int fl = tid + 256 * j, r = fl >> 3, u = fl & 7;
            const float* ws = (r < 128) ? (th_w + (size_t)r * CH)
                            : (r < 256) ? (ph_w + (size_t)(r - 128) * CH)
                                        : (g_w + (size_t)(r - 256) * CH);
            *(float4*)(Ws + r * 36 + 4 * u) = *(const float4*)(ws + c0 + 4 * u);
        }
        __syncthreads();
        #pragma unroll 8
        for (int c = 0; c < 32; c++) {
            float4 xv = *(const float4*)(Xs + (c0 + c) * 32 + 4 * tx);
            #pragma unroll
            for (int m = 0; m < 12; m++) {
                float w = Ws[(ty + 32 * m) * 36 + c];
                acc[m][0] += w * xv.x; acc[m][1] += w * xv.y;
                acc[m][2] += w * xv.z; acc[m][3] += w * xv.w;
            }
        }
    }
    __syncthreads();
    float* Sm = sm1;   // [384][33]
    #pragma unroll
    for (int m = 0; m < 12; m++) {
        int r = ty + 32 * m;
        #pragma unroll
        for (int j = 0; j < 4; j++) Sm[r * 33 + 4 * tx + j] = acc[m][j];
    }
    __syncthreads();
    const size_t bN = (size_t)b * NTOK;
    #pragma unroll
    for (int it = 0; it < 4; it++) {   // theta/phi: [n][ic] rows
        int idx = tid + 256 * it;
        int t = idx >> 9, rem = idx & 511, n = rem >> 4, seg = rem & 15;
        uint32_t hp[4], lp[4];
        #pragma unroll
        for (int j = 0; j < 4; j++) {
            float a = Sm[(t * 128 + seg * 8 + 2 * j) * 33 + n];
            float c = Sm[(t * 128 + seg * 8 + 2 * j + 1) * 33 + n];
            __nv_bfloat16 ha = __float2bfloat16(a), hc = __float2bfloat16(c);
            CVT2(hp[j], a, c);
            CVT2(lp[j], a - __bfloat162float(ha), c - __bfloat162float(hc));
        }
        __nv_bfloat16* hi = t ? g_ph_hi : g_th_hi;
        __nv_bfloat16* lo = t ? g_ph_lo : g_th_lo;
        size_t base = (bN + n0 + n) * IC + seg * 8;
        *(uint4*)(hi + base) = make_uint4(hp[0], hp[1], hp[2], hp[3]);
        *(uint4*)(lo + base) = make_uint4(lp[0], lp[1], lp[2], lp[3]);
    }
    #pragma unroll
    for (int it = 0; it < 2; it++) {   // g transposed: [ic][n]
        int idx = tid + 256 * it, ic = idx >> 2, ch = idx & 3;
        uint32_t hp[4], lp[4];
        #pragma unroll
        for (int j = 0; j < 4; j++) {
            float a = Sm[(256 + ic) * 33 + ch * 8 + 2 * j];
            float c = Sm[(256 + ic) * 33 + ch * 8 + 2 * j + 1];
            __nv_bfloat16 ha = __float2bfloat16(a), hc = __float2bfloat16(c);
            CVT2(hp[j], a, c);
            CVT2(lp[j], a - __bfloat162float(ha), c - __bfloat162float(hc));
        }
        size_t base = ((size_t)b * IC + ic) * NTOK + n0 + ch * 8;
        *(uint4*)(g_g_hi + base) = make_uint4(hp[0], hp[1], hp[2], hp[3]);
        *(uint4*)(g_g_lo + base) = make_uint4(lp[0], lp[1], lp[2], lp[3]);
    }
}

// ---------------------------------------------------------------------------
// Kernel 2: mma.sync flash attention, cp.async pipelined, + fused out-proj.
// 256 thr, grid (32,8). Buffer-reuse pipeline:
//   K(kt+1) prefetched during softmax+PV(kt); G(kt+1) during S(kt+1).
// ---------------------------------------------------------------------------
#define O_QHI 0
#define O_QLO 34816
#define O_KHI 69632
#define O_KLO 87040
#define O_GHI 104448
#define O_GLO 122880
#define O_PHI 141312
#define O_PLO 159744
#define O_OS 0
#define O_WT 69632
#define O_RED 202752
#define SMEM_ATTN 203776

__global__ void __launch_bounds__(256, 1)
attn_kernel(const float* __restrict__ x, const float* __restrict__ Ww,
            const float* __restrict__ Wb, float* __restrict__ out)
{
    extern __shared__ char smc[];
    const int b = blockIdx.y, q0 = blockIdx.x * 128, tid = threadIdx.x;
    const int lane = tid & 31, wid = tid >> 5;
    const int wq = wid & 3, wk = wid >> 2;
    const int lr = lane >> 2, lc = lane & 3;
    const int qb = 32 * wq, kb = 32 * wk, ib = 64 * wk;
    const size_t bN = (size_t)b * NTOK;
    float* red = (float*)(smc + O_RED);
    const uint32_t smb = (uint32_t)__cvta_generic_to_shared(smc);

    // cp.async issuers: one commit group each.
    auto issue_K = [&](int kt) {
        const int k0 = kt * 64;
        #pragma unroll
        for (int j = 0; j < 8; j++) {
            int idx = tid + 256 * j;
            int plane = idx >> 10, e = idx & 1023, row = e >> 4, seg = e & 15;
            const __nv_bfloat16* src = (plane ? g_ph_lo : g_ph_hi) + (bN + k0 + row) * IC + seg * 8;
            uint32_t dst = smb + (plane ? O_KLO : O_KHI) + row * 272 + seg * 16;
            CP16(dst, src);
        }
        CP_COMMIT();
    };
    auto issue_G = [&](int kt) {
        const int k0 = kt * 64;
        #pragma unroll
        for (int j = 0; j < 8; j++) {
            int idx = tid + 256 * j;
            int plane = idx >> 10, e = idx & 1023, row = e >> 3, seg = e & 7;
            const __nv_bfloat16* src = (plane ? g_g_lo : g_g_hi) + ((size_t)b * IC + row) * NTOK + k0 + seg * 8;
            uint32_t dst = smb + (plane ? O_GLO : O_GHI) + row * 144 + seg * 16;
            CP16(dst, src);
        }
        CP_COMMIT();
    };

    // ---- Q tile -> smem (hi/lo), padded rows 272B ----
    #pragma unroll
    for (int j = 0; j < 16; j++) {
        int idx = tid + 256 * j;
        int plane = idx >> 11, e = idx & 2047, row = e >> 4, seg = e & 15;
        const __nv_bfloat16* src = (plane ? g_th_lo : g_th_hi) + (bN + q0 + row) * IC + seg * 8;
        *(uint4*)(smc + (plane ? O_QLO : O_QHI) + row * 272 + seg * 16) = *(const uint4*)src;
    }
    issue_K(0);
    issue_G(0);
    CP_WAIT(0);
    __syncthreads();

    float Ofr[2][8][4] = {};
    float lsum[4] = {0.f, 0.f, 0.f, 0.f};
    float M[4];

    for (int kt = 0; kt < NTOK / 64; kt++) {
        // ---- S = Q K^T (warp: 32q x 32key), 3-term bf16 split ----
        float S[2][4][4] = {};
        #pragma unroll
        for (int ks = 0; ks < 8; ks++) {
            uint32_t ah[2][4], al[2][4];
            #pragma unroll
            for (int mt = 0; mt < 2; mt++) {
                int ro = (qb + 16 * mt + lr) * 272 + 32 * ks + 4 * lc;
                ah[mt][0] = *(const uint32_t*)(smc + O_QHI + ro);
                ah[mt][1] = *(const uint32_t*)(smc + O_QHI + ro + 8 * 272);
                ah[mt][2] = *(const uint32_t*)(smc + O_QHI + ro + 16);
                ah[mt][3] = *(const uint32_t*)(smc + O_QHI + ro + 8 * 272 + 16);
                al[mt][0] = *(const uint32_t*)(smc + O_QLO + ro);
                al[mt][1] = *(const uint32_t*)(smc + O_QLO + ro + 8 * 272);
                al[mt][2] = *(const uint32_t*)(smc + O_QLO + ro + 16);
                al[mt][3] = *(const uint32_t*)(smc + O_QLO + ro + 8 * 272 + 16);
            }
            #pragma unroll
            for (int nt = 0; nt < 4; nt++) {
                int ro = (kb + 8 * nt + lr) * 272 + 32 * ks + 4 * lc;
                uint32_t bh0 = *(const uint32_t*)(smc + O_KHI + ro);
                uint32_t bh1 = *(const uint32_t*)(smc + O_KHI + ro + 16);
                uint32_t bl0 = *(const uint32_t*)(smc + O_KLO + ro);
                uint32_t bl1 = *(const uint32_t*)(smc + O_KLO + ro + 16);
                #pragma unroll
                for (int mt = 0; mt < 2; mt++) {
                    mma_bf16(S[mt][nt], ah[mt][0], ah[mt][1], ah[mt][2], ah[mt][3], bh0, bh1);
                    mma_bf16(S[mt][nt], ah[mt][0], ah[mt][1], ah[mt][2], ah[mt][3], bl0, bl1);
                    mma_bf16(S[mt][nt], al[mt][0], al[mt][1], al[mt][2], al[mt][3], bh0, bh1);
                }
            }
        }
        __syncthreads();                         // all warps done reading K(kt)
        if (kt < NTOK / 64 - 1) issue_K(kt + 1); // prefetch K(kt+1) over softmax+PV

        if (kt == 0) {   // fixed reference max from tile 0
            #pragma unroll
            for (int mt = 0; mt < 2; mt++) {
                float m0 = -1e30f, m1 = -1e30f;
                #pragma unroll
                for (int nt = 0; nt < 4; nt++) {
                    m0 = fmaxf(m0, fmaxf(S[mt][nt][0], S[mt][nt][1]));
                    m1 = fmaxf(m1, fmaxf(S[mt][nt][2], S[mt][nt][3]));
                }
                m0 = fmaxf(m0, __shfl_xor_sync(0xffffffffu, m0, 1));
                m0 = fmaxf(m0, __shfl_xor_sync(0xffffffffu, m0, 2));
                m1 = fmaxf(m1, __shfl_xor_sync(0xffffffffu, m1, 1));
                m1 = fmaxf(m1, __shfl_xor_sync(0xffffffffu, m1, 2));
                if (lc == 0) {
                    red[wk * 128 + qb + 16 * mt + lr] = m0;
                    red[wk * 128 + qb + 16 * mt + lr + 8] = m1;
                }
            }
            __syncthreads();
            #pragma unroll
            for (int mt = 0; mt < 2; mt++) {
                M[2 * mt]     = fmaxf(red[qb + 16 * mt + lr],     red[128 + qb + 16 * mt + lr]);
                M[2 * mt + 1] = fmaxf(red[qb + 16 * mt + lr + 8], red[128 + qb + 16 * mt + lr + 8]);
            }
        }

        // ---- P = exp(S - M), bf16 hi/lo -> smem ----
        #pragma unroll
        for (int mt = 0; mt < 2; mt++) {
            int r0 = (qb + 16 * mt + lr) * 144 + kb * 2 + lc * 4;  // byte offset, stride 144
            #pragma unroll
            for (int nt = 0; nt < 4; nt++) {
                float p00 = fexp(S[mt][nt][0] - M[2 * mt]);
                float p01 = fexp(S[mt][nt][1] - M[2 * mt]);
                float p10 = fexp(S[mt][nt][2] - M[2 * mt + 1]);
                float p11 = fexp(S[mt][nt][3] - M[2 * mt + 1]);
                lsum[2 * mt] += p00 + p01;
                lsum[2 * mt + 1] += p10 + p11;
                uint32_t h0, h1, l0, l1;
                __nv_bfloat16 c0 = __float2bfloat16(p00), c1 = __float2bfloat16(p01);
                __nv_bfloat16 c2 = __float2bfloat16(p10), c3 = __float2bfloat16(p11);
                CVT2(h0, p00, p01); CVT2(h1, p10, p11);
                CVT2(l0, p00 - __bfloat162float(c0), p01 - __bfloat162float(c1));
                CVT2(l1, p10 - __bfloat162float(c2), p11 - __bfloat162float(c3));
                *(uint32_t*)(smc + O_PHI + r0 + 16 * nt) = h0;
                *(uint32_t*)(smc + O_PHI + r0 + 16 * nt + 8 * 144) = h1;
                *(uint32_t*)(smc + O_PLO + r0 + 16 * nt) = l0;
                *(uint32_t*)(smc + O_PLO + r0 + 16 * nt + 8 * 144) = l1;
            }
        }
        if (kt < NTOK / 64 - 1) { CP_WAIT(1); } else { CP_WAIT(0); }  // G(kt) done
        __syncthreads();                         // P visible; G(kt) visible

        // ---- O += P G^T (warp: 32q x 64i), 3-term ----
        #pragma unroll
        for (int ks = 0; ks < 4; ks++) {
            uint32_t ph[2][4], pl[2][4];
            #pragma unroll
            for (int mt = 0; mt < 2; mt++) {
                int ro = (qb + 16 * mt + lr) * 144 + 32 * ks + 4 * lc;
                ph[mt][0] = *(const uint32_t*)(smc + O_PHI + ro);
                ph[mt][1] = *(const uint32_t*)(smc + O_PHI + ro + 8 * 144);
                ph[mt][2] = *(const uint32_t*)(smc + O_PHI + ro + 16);
                ph[mt][3] = *(const uint32_t*)(smc + O_PHI + ro + 8 * 144 + 16);
                pl[mt][0] = *(const uint32_t*)(smc + O_PLO + ro);
                pl[mt][1] = *(const uint32_t*)(smc + O_PLO + ro + 8 * 144);
                pl[mt][2] = *(const uint32_t*)(smc + O_PLO + ro + 16);
                pl[mt][3] = *(const uint32_t*)(smc + O_PLO + ro + 8 * 144 + 16);
            }
            #pragma unroll
            for (int nt = 0; nt < 8; nt++) {
                int ro = (ib + 8 * nt + lr) * 144 + 32 * ks + 4 * lc;
                uint32_t gh0 = *(const uint32_t*)(smc + O_GHI + ro);
                uint32_t gh1 = *(const uint32_t*)(smc + O_GHI + ro + 16);
                uint32_t gl0 = *(const uint32_t*)(smc + O_GLO + ro);
                uint32_t gl1 = *(const uint32_t*)(smc + O_GLO + ro + 16);
                #pragma unroll
                for (int mt = 0; mt < 2; mt++) {
                    mma_bf16(Ofr[mt][nt], ph[mt][0], ph[mt][1], ph[mt][2], ph[mt][3], gh0, gh1);
                    mma_bf16(Ofr[mt][nt], ph[mt][0], ph[mt][1], ph[mt][2], ph[mt][3], gl0, gl1);
                    mma_bf16(Ofr[mt][nt], pl[mt][0], pl[mt][1], pl[mt][2], pl[mt][3], gh0, gh1);
                }
            }
        }
        __syncthreads();                          // all done reading P & G(kt)
        if (kt < NTOK / 64 - 1) {
            issue_G(kt + 1);                      // prefetch G(kt+1) over S(kt+1)
            CP_WAIT(1);                           // K(kt+1) complete (G may fly)
        }
        __syncthreads();                          // K(kt+1) visible to all
    }

    // ---- l reduce, normalize, write Os[i][q] fp32 ----
    #pragma unroll
    for (int v = 0; v < 4; v++) {
        lsum[v] += __shfl_xor_sync(0xffffffffu, lsum[v], 1);
        lsum[v] += __shfl_xor_sync(0xffffffffu, lsum[v], 2);
    }
    if (lc == 0) {
        #pragma unroll
        for (int mt = 0; mt < 2; mt++) {
            red[wk * 128 + qb + 16 * mt + lr] = lsum[2 * mt];
            red[wk * 128 + qb + 16 * mt + lr + 8] = lsum[2 * mt + 1];
        }
    }
    __syncthreads();
    float inv[4];
    #pragma unroll
    for (int mt = 0; mt < 2; mt++) {
        inv[2 * mt]     = 1.f / (red[qb + 16 * mt + lr]     + red[128 + qb + 16 * mt + lr]);
        inv[2 * mt + 1] = 1.f / (red[qb + 16 * mt + lr + 8] + red[128 + qb + 16 * mt + lr + 8]);
    }
    __syncthreads();
    float* Os = (float*)(smc + O_OS);   // [128 i][132], aliases Q (dead)
    #pragma unroll
    for (int mt = 0; mt < 2; mt++)
        #pragma unroll
        for (int nt = 0; nt < 8; nt++)
            #pragma unroll
            for (int j = 0; j < 4; j++) {
                int q = qb + 16 * mt + lr + 8 * (j >> 1);
                int i = ib + 8 * nt + 2 * lc + (j & 1);
                Os[i * 132 + q] = Ofr[mt][nt][j] * inv[2 * mt + (j >> 1)];
            }
    float* Wt = (float*)(smc + O_WT);   // [128 i][260] = Ww^T, aliases K/G/P (dead)
    #pragma unroll
    for (int j = 0; j < 32; j++) {
        int fl = tid + 256 * j, c = fl >> 5, i4 = (fl & 31) * 4;
        float4 v = *(const float4*)(Ww + (size_t)c * IC + i4);
        Wt[(i4 + 0) * 260 + c] = v.x; Wt[(i4 + 1) * 260 + c] = v.y;
        Wt[(i4 + 2) * 260 + c] = v.z; Wt[(i4 + 3) * 260 + c] = v.w;
    }
    __syncthreads();

    // ---- out[c][q] = Ww Os + b + x (fp32 SIMT) ----
    const int tx = tid & 15, ty = tid >> 4;
    for (int qh = 0; qh < 2; qh++) {
        float acc[16][4];
        #pragma unroll
        for (int cc = 0; cc < 16; cc++)
            acc[cc][0] = acc[cc][1] = acc[cc][2] = acc[cc][3] = 0.f;
        #pragma unroll 4
        for (int i = 0; i < 128; i++) {
            float4 ov = *(const float4*)(Os + i * 132 + qh * 64 + 4 * tx);
            #pragma unroll
            for (int cc = 0; cc < 16; cc++) {
                float w = Wt[i * 260 + ty + 16 * cc];
                acc[cc][0] += w * ov.x; acc[cc][1] += w * ov.y;
                acc[cc][2] += w * ov.z; acc[cc][3] += w * ov.w;
            }
        }
        #pragma unroll
        for (int cc = 0; cc < 16; cc++) {
            int c = ty + 16 * cc;
            float wb = Wb[c];
            size_t base = ((size_t)b * CH + c) * NTOK + q0 + qh * 64 + 4 * tx;
            float4 xr = *(const float4*)(x + base);
            float4 o;
            o.x = acc[cc][0] + wb + xr.x; o.y = acc[cc][1] + wb + xr.y;
            o.z = acc[cc][2] + wb + xr.z; o.w = acc[cc][3] + wb + xr.w;
            *(float4*)(out + base) = o;
        }
    }
}

// ---------------------------------------------------------------------------
extern "C" void kernel_launch(void* const* d_in, const int* in_sizes, int n_in,
                              void* d_out, int out_size)
{
    const float* x    = (const float*)d_in[0];
    const float* g_w  = (const float*)d_in[1];
    const float* g_b  = (const float*)d_in[2];
    const float* th_w = (const float*)d_in[3];
    const float* th_b = (const float*)d_in[4];
    const float* ph_w = (const float*)d_in[5];
    const float* ph_b = (const float*)d_in[6];
    const float* W_w  = (const float*)d_in[7];
    const float* W_b  = (const float*)d_in[8];
    float* out = (float*)d_out;

    const int SMEM1 = (256 * 32 + 384 * 36) * 4;
    cudaFuncSetAttribute(proj_kernel, cudaFuncAttributeMaxDynamicSharedMemorySize, SMEM1);
    cudaFuncSetAttribute(attn_kernel, cudaFuncAttributeMaxDynamicSharedMemorySize, SMEM_ATTN);

    proj_kernel<<<dim3(NTOK / 32, BATCH), 256, SMEM1>>>(
        x, th_w, th_b, ph_w, ph_b, g_w, g_b);
    attn_kernel<<<dim3(NTOK / 128, BATCH), 256, SMEM_ATTN>>>(
        x, W_w, W_b, out);
}

// round 13
// speedup vs baseline: 2.9955x; 1.0262x over previous
#include <cuda_runtime.h>
#include <cuda_bf16.h>
#include <cstdint>
#include <math.h>

#define CH 256
#define IC 128
#define BATCH 8
#define NTOK 4096

// bf16 hi/lo planes. th/ph: [b][n][ic]; g: [b][ic][n].
__device__ __align__(16) __nv_bfloat16 g_th_hi[(size_t)BATCH * NTOK * IC];
__device__ __align__(16) __nv_bfloat16 g_th_lo[(size_t)BATCH * NTOK * IC];
__device__ __align__(16) __nv_bfloat16 g_ph_hi[(size_t)BATCH * NTOK * IC];
__device__ __align__(16) __nv_bfloat16 g_ph_lo[(size_t)BATCH * NTOK * IC];
__device__ __align__(16) __nv_bfloat16 g_g_hi[(size_t)BATCH * NTOK * IC];
__device__ __align__(16) __nv_bfloat16 g_g_lo[(size_t)BATCH * NTOK * IC];

#define CVT2(r, a, b) asm("cvt.rn.satfinite.bf16x2.f32 %0, %1, %2;" : "=r"(r) : "f"(b), "f"(a))
#define CP16(d, s) asm volatile("cp.async.cg.shared.global [%0], [%1], 16;" :: "r"(d), "l"(s) : "memory")
#define CP_COMMIT() asm volatile("cp.async.commit_group;" ::: "memory")
#define CP_WAIT(n) asm volatile("cp.async.wait_group %0;" :: "n"(n) : "memory")
#define LDSM4(r0, r1, r2, r3, a) \
    asm volatile("ldmatrix.sync.aligned.m8n8.x4.shared.b16 {%0,%1,%2,%3}, [%4];" \
        : "=r"(r0), "=r"(r1), "=r"(r2), "=r"(r3) : "r"(a))

__device__ __forceinline__ void mma_bf16(float d[4], uint32_t a0, uint32_t a1,
                                         uint32_t a2, uint32_t a3,
                                         uint32_t b0, uint32_t b1) {
    asm volatile(
        "mma.sync.aligned.m16n8k16.row.col.f32.bf16.bf16.f32 "
        "{%0,%1,%2,%3},{%4,%5,%6,%7},{%8,%9},{%0,%1,%2,%3};"
        : "+f"(d[0]), "+f"(d[1]), "+f"(d[2]), "+f"(d[3])
        : "r"(a0), "r"(a1), "r"(a2), "r"(a3), "r"(b0), "r"(b1));
}

// exp(x) on the FMA pipe (no MUFU): 2^(x*log2e), round trick + deg-5 poly.
__device__ __forceinline__ float fexp(float x) {
    float y = x * 1.44269504089f;
    float z = y + 12582912.0f;               // 1.5*2^23
    int n = __float_as_int(z) - 0x4B400000;
    float f = y - (z - 12582912.0f);         // f in [-0.5, 0.5]
    float p = 1.33336e-3f;
    p = fmaf(p, f, 9.61813e-3f);
    p = fmaf(p, f, 5.550411e-2f);
    p = fmaf(p, f, 2.4022651e-1f);
    p = fmaf(p, f, 6.9314718e-1f);
    p = fmaf(p, f, 1.0f);
    return __int_as_float(__float_as_int(p) + (n << 23));
}

// ---------------------------------------------------------------------------
// Kernel 1: fp32 projections -> bf16 hi/lo planes (smem transpose for stores)
// ---------------------------------------------------------------------------
__global__ void proj_kernel(const float* __restrict__ x,
                            const float* __restrict__ th_w, const float* __restrict__ th_b,
                            const float* __restrict__ ph_w, const float* __restrict__ ph_b,
                            const float* __restrict__ g_w,  const float* __restrict__ g_b)
{
    extern __shared__ float sm1[];
    float* Xs = sm1;              // [256][32]
    float* Ws = sm1 + 8192;       // [384][36]
    const int b = blockIdx.y, n0 = blockIdx.x * 32, tid = threadIdx.x;
    const int tx = tid & 7, ty = tid >> 3;

    const float* xb = x + (size_t)b * CH * NTOK;
    #pragma unroll
    for (int j = 0; j < 8; j++) {
        int fl = tid + 256 * j, c = fl >> 3, u = fl & 7;
        *(float4*)(Xs + c * 32 + 4 * u) = *(const float4*)(xb + (size_t)c * NTOK + n0 + 4 * u);
    }
    float acc[12][4];
    #pragma unroll
    for (int m = 0; m < 12; m++) {
        int r = ty + 32 * m;
        float bias = (r < 128) ? th_b[r] : (r < 256 ? ph_b[r - 128] : g_b[r - 256]);
        acc[m][0] = acc[m][1] = acc[m][2] = acc[m][3] = bias;
    }
    for (int c0 = 0; c0 < 256; c0 += 32) {
        __syncthreads();
        #pragma unroll
        for (int j = 0; j < 12; j++) {
            int fl = tid + 256 * j, r = fl >> 3, u = fl & 7;
            const float* ws = (r < 128) ? (th_w + (size_t)r * CH)
                            : (r < 256) ? (ph_w + (size_t)(r - 128) * CH)
                                        : (g_w + (size_t)(r - 256) * CH);
            *(float4*)(Ws + r * 36 + 4 * u) = *(const float4*)(ws + c0 + 4 * u);
        }
        __syncthreads();
        #pragma unroll 8
        for (int c = 0; c < 32; c++) {
            float4 xv = *(const float4*)(Xs + (c0 + c) * 32 + 4 * tx);
            #pragma unroll
            for (int m = 0; m < 12; m++) {
                float w = Ws[(ty + 32 * m) * 36 + c];
                acc[m][0] += w * xv.x; acc[m][1] += w * xv.y;
                acc[m][2] += w * xv.z; acc[m][3] += w * xv.w;
            }
        }
    }
    __syncthreads();
    float* Sm = sm1;   // [384][33]
    #pragma unroll
    for (int m = 0; m < 12; m++) {
        int r = ty + 32 * m;
        #pragma unroll
        for (int j = 0; j < 4; j++) Sm[r * 33 + 4 * tx + j] = acc[m][j];
    }
    __syncthreads();
    const size_t bN = (size_t)b * NTOK;
    #pragma unroll
    for (int it = 0; it < 4; it++) {   // theta/phi: [n][ic] rows
        int idx = tid + 256 * it;
        int t = idx >> 9, rem = idx & 511, n = rem >> 4, seg = rem & 15;
        uint32_t hp[4], lp[4];
        #pragma unroll
        for (int j = 0; j < 4; j++) {
            float a = Sm[(t * 128 + seg * 8 + 2 * j) * 33 + n];
            float c = Sm[(t * 128 + seg * 8 + 2 * j + 1) * 33 + n];
            __nv_bfloat16 ha = __float2bfloat16(a), hc = __float2bfloat16(c);
            CVT2(hp[j], a, c);
            CVT2(lp[j], a - __bfloat162float(ha), c - __bfloat162float(hc));
        }
        __nv_bfloat16* hi = t ? g_ph_hi : g_th_hi;
        __nv_bfloat16* lo = t ? g_ph_lo : g_th_lo;
        size_t base = (bN + n0 + n) * IC + seg * 8;
        *(uint4*)(hi + base) = make_uint4(hp[0], hp[1], hp[2], hp[3]);
        *(uint4*)(lo + base) = make_uint4(lp[0], lp[1], lp[2], lp[3]);
    }
    #pragma unroll
    for (int it = 0; it < 2; it++) {   // g transposed: [ic][n]
        int idx = tid + 256 * it, ic = idx >> 2, ch = idx & 3;
        uint32_t hp[4], lp[4];
        #pragma unroll
        for (int j = 0; j < 4; j++) {
            float a = Sm[(256 + ic) * 33 + ch * 8 + 2 * j];
            float c = Sm[(256 + ic) * 33 + ch * 8 + 2 * j + 1];
            __nv_bfloat16 ha = __float2bfloat16(a), hc = __float2bfloat16(c);
            CVT2(hp[j], a, c);
            CVT2(lp[j], a - __bfloat162float(ha), c - __bfloat162float(hc));
        }
        size_t base = ((size_t)b * IC + ic) * NTOK + n0 + ch * 8;
        *(uint4*)(g_g_hi + base) = make_uint4(hp[0], hp[1], hp[2], hp[3]);
        *(uint4*)(g_g_lo + base) = make_uint4(lp[0], lp[1], lp[2], lp[3]);
    }
}

// ---------------------------------------------------------------------------
// Kernel 2: mma.sync flash attention, cp.async pipelined, ldmatrix frags,
// + fused out-proj. 256 thr, grid (32,8).
// ---------------------------------------------------------------------------
#define O_QHI 0
#define O_QLO 34816
#define O_KHI 69632
#define O_KLO 87040
#define O_GHI 104448
#define O_GLO 122880
#define O_PHI 141312
#define O_PLO 159744
#define O_OS 0
#define O_WT 69632
#define O_RED 202752
#define SMEM_ATTN 203776

__global__ void __launch_bounds__(256, 1)
attn_kernel(const float* __restrict__ x, const float* __restrict__ Ww,
            const float* __restrict__ Wb, float* __restrict__ out)
{
    extern __shared__ char smc[];
    const int b = blockIdx.y, q0 = blockIdx.x * 128, tid = threadIdx.x;
    const int lane = tid & 31, wid = tid >> 5;
    const int wq = wid & 3, wk = wid >> 2;
    const int lr = lane >> 2, lc = lane & 3;
    const int qb = 32 * wq, kb = 32 * wk, ib = 64 * wk;
    const size_t bN = (size_t)b * NTOK;
    float* red = (float*)(smc + O_RED);
    const uint32_t smb = (uint32_t)__cvta_generic_to_shared(smc);

    // ldmatrix row/col selectors (computed once)
    const int arow = (lane & 7) + ((lane >> 3) & 1) * 8;  // A-type x4
    const int acol = (lane >> 4) * 16;
    const int brow = (lane & 7) + (lane >> 4) * 8;        // B-type x4 (2 nt per ldsm)
    const int bcol = ((lane >> 3) & 1) * 16;

    // cp.async issuers: one commit group each.
    auto issue_K = [&](int kt) {
        const int k0 = kt * 64;
        #pragma unroll
        for (int j = 0; j < 8; j++) {
            int idx = tid + 256 * j;
            int plane = idx >> 10, e = idx & 1023, row = e >> 4, seg = e & 15;
            const __nv_bfloat16* src = (plane ? g_ph_lo : g_ph_hi) + (bN + k0 + row) * IC + seg * 8;
            uint32_t dst = smb + (plane ? O_KLO : O_KHI) + row * 272 + seg * 16;
            CP16(dst, src);
        }
        CP_COMMIT();
    };
    auto issue_G = [&](int kt) {
        const int k0 = kt * 64;
        #pragma unroll
        for (int j = 0; j < 8; j++) {
            int idx = tid + 256 * j;
            int plane = idx >> 10, e = idx & 1023, row = e >> 3, seg = e & 7;
            const __nv_bfloat16* src = (plane ? g_g_lo : g_g_hi) + ((size_t)b * IC + row) * NTOK + k0 + seg * 8;
            uint32_t dst = smb + (plane ? O_GLO : O_GHI) + row * 144 + seg * 16;
            CP16(dst, src);
        }
        CP_COMMIT();
    };

    // ---- Q tile -> smem (hi/lo), padded rows 272B ----
    #pragma unroll
    for (int j = 0; j < 16; j++) {
        int idx = tid + 256 * j;
        int plane = idx >> 11, e = idx & 2047, row = e >> 4, seg = e & 15;
        const __nv_bfloat16* src = (plane ? g_th_lo : g_th_hi) + (bN + q0 + row) * IC + seg * 8;
        *(uint4*)(smc + (plane ? O_QLO : O_QHI) + row * 272 + seg * 16) = *(const uint4*)src;
    }
    issue_K(0);
    issue_G(0);
    CP_WAIT(0);
    __syncthreads();

    float Ofr[2][8][4] = {};
    float lsum[4] = {0.f, 0.f, 0.f, 0.f};
    float M[4];

    for (int kt = 0; kt < NTOK / 64; kt++) {
        // ---- S = Q K^T (warp: 32q x 32key), 3-term bf16 split ----
        float S[2][4][4] = {};
        #pragma unroll
        for (int ks = 0; ks < 8; ks++) {
            uint32_t ah[2][4], al[2][4], bh[4][2], bl[4][2];
            #pragma unroll
            for (int mt = 0; mt < 2; mt++) {
                uint32_t ab = (uint32_t)((qb + 16 * mt + arow) * 272 + 32 * ks + acol);
                LDSM4(ah[mt][0], ah[mt][1], ah[mt][2], ah[mt][3], smb + O_QHI + ab);
                LDSM4(al[mt][0], al[mt][1], al[mt][2], al[mt][3], smb + O_QLO + ab);
            }
            #pragma unroll
            for (int np = 0; np < 2; np++) {
                uint32_t bb = (uint32_t)((kb + 16 * np + brow) * 272 + 32 * ks + bcol);
                LDSM4(bh[2 * np][0], bh[2 * np][1], bh[2 * np + 1][0], bh[2 * np + 1][1],
                      smb + O_KHI + bb);
                LDSM4(bl[2 * np][0], bl[2 * np][1], bl[2 * np + 1][0], bl[2 * np + 1][1],
                      smb + O_KLO + bb);
            }
            #pragma unroll
            for (int nt = 0; nt < 4; nt++)
                #pragma unroll
                for (int mt = 0; mt < 2; mt++) {
                    mma_bf16(S[mt][nt], ah[mt][0], ah[mt][1], ah[mt][2], ah[mt][3],
                             bh[nt][0], bh[nt][1]);
                    mma_bf16(S[mt][nt], ah[mt][0], ah[mt][1], ah[mt][2], ah[mt][3],
                             bl[nt][0], bl[nt][1]);
                    mma_bf16(S[mt][nt], al[mt][0], al[mt][1], al[mt][2], al[mt][3],
                             bh[nt][0], bh[nt][1]);
                }
        }
        __syncthreads();                         // all warps done reading K(kt)
        if (kt < NTOK / 64 - 1) issue_K(kt + 1); // prefetch K(kt+1) over softmax+PV

        if (kt == 0) {   // fixed reference max from tile 0
            #pragma unroll
            for (int mt = 0; mt < 2; mt++) {
                float m0 = -1e30f, m1 = -1e30f;
                #pragma unroll
                for (int nt = 0; nt < 4; nt++) {
                    m0 = fmaxf(m0, fmaxf(S[mt][nt][0], S[mt][nt][1]));
                    m1 = fmaxf(m1, fmaxf(S[mt][nt][2], S[mt][nt][3]));
                }
                m0 = fmaxf(m0, __shfl_xor_sync(0xffffffffu, m0, 1));
                m0 = fmaxf(m0, __shfl_xor_sync(0xffffffffu, m0, 2));
                m1 = fmaxf(m1, __shfl_xor_sync(0xffffffffu, m1, 1));
                m1 = fmaxf(m1, __shfl_xor_sync(0xffffffffu, m1, 2));
                if (lc == 0) {
                    red[wk * 128 + qb + 16 * mt + lr] = m0;
                    red[wk * 128 + qb + 16 * mt + lr + 8] = m1;
                }
            }
            __syncthreads();
            #pragma unroll
            for (int mt = 0; mt < 2; mt++) {
                M[2 * mt]     = fmaxf(red[qb + 16 * mt + lr],     red[128 + qb + 16 * mt + lr]);
                M[2 * mt + 1] = fmaxf(red[qb + 16 * mt + lr + 8], red[128 + qb + 16 * mt + lr + 8]);
            }
        }

        // ---- P = exp(S - M), bf16 hi/lo -> smem ----
        #pragma unroll
        for (int mt = 0; mt < 2; mt++) {
            int r0 = (qb + 16 * mt + lr) * 144 + kb * 2 + lc * 4;  // byte offset, stride 144
            #pragma unroll
            for (int nt = 0; nt < 4; nt++) {
                float p00 = fexp(S[mt][nt][0] - M[2 * mt]);
                float p01 = fexp(S[mt][nt][1] - M[2 * mt]);
                float p10 = fexp(S[mt][nt][2] - M[2 * mt + 1]);
                float p11 = fexp(S[mt][nt][3] - M[2 * mt + 1]);
                lsum[2 * mt] += p00 + p01;
                lsum[2 * mt + 1] += p10 + p11;
                uint32_t h0, h1, l0, l1;
                __nv_bfloat16 c0 = __float2bfloat16(p00), c1 = __float2bfloat16(p01);
                __nv_bfloat16 c2 = __float2bfloat16(p10), c3 = __float2bfloat16(p11);
                CVT2(h0, p00, p01); CVT2(h1, p10, p11);
                CVT2(l0, p00 - __bfloat162float(c0), p01 - __bfloat162float(c1));
                CVT2(l1, p10 - __bfloat162float(c2), p11 - __bfloat162float(c3));
                *(uint32_t*)(smc + O_PHI + r0 + 16 * nt) = h0;
                *(uint32_t*)(smc + O_PHI + r0 + 16 * nt + 8 * 144) = h1;
                *(uint32_t*)(smc + O_PLO + r0 + 16 * nt) = l0;
                *(uint32_t*)(smc + O_PLO + r0 + 16 * nt + 8 * 144) = l1;
            }
        }
        if (kt < NTOK / 64 - 1) { CP_WAIT(1); } else { CP_WAIT(0); }  // G(kt) done
        __syncthreads();                         // P visible; G(kt) visible

        // ---- O += P G^T (warp: 32q x 64i), 3-term ----
        #pragma unroll
        for (int ks = 0; ks < 4; ks++) {
            uint32_t ph[2][4], pl[2][4], gh[8][2], gl[8][2];
            #pragma unroll
            for (int mt = 0; mt < 2; mt++) {
                uint32_t pb = (uint32_t)((qb + 16 * mt + arow) * 144 + 32 * ks + acol);
                LDSM4(ph[mt][0], ph[mt][1], ph[mt][2], ph[mt][3], smb + O_PHI + pb);
                LDSM4(pl[mt][0], pl[mt][1], pl[mt][2], pl[mt][3], smb + O_PLO + pb);
            }
            #pragma unroll
            for (int np = 0; np < 4; np++) {
                uint32_t gb = (uint32_t)((ib + 16 * np + brow) * 144 + 32 * ks + bcol);
                LDSM4(gh[2 * np][0], gh[2 * np][1], gh[2 * np + 1][0], gh[2 * np + 1][1],
                      smb + O_GHI + gb);
                LDSM4(gl[2 * np][0], gl[2 * np][1], gl[2 * np + 1][0], gl[2 * np + 1][1],
                      smb + O_GLO + gb);
            }
            #pragma unroll
            for (int nt = 0; nt < 8; nt++)
                #pragma unroll
                for (int mt = 0; mt < 2; mt++) {
                    mma_bf16(Ofr[mt][nt], ph[mt][0], ph[mt][1], ph[mt][2], ph[mt][3],
                             gh[nt][0], gh[nt][1]);
                    mma_bf16(Ofr[mt][nt], ph[mt][0], ph[mt][1], ph[mt][2], ph[mt][3],
                             gl[nt][0], gl[nt][1]);
                    mma_bf16(Ofr[mt][nt], pl[mt][0], pl[mt][1], pl[mt][2], pl[mt][3],
                             gh[nt][0], gh[nt][1]);
                }
        }
        __syncthreads();                          // all done reading P & G(kt)
        if (kt < NTOK / 64 - 1) {
            issue_G(kt + 1);                      // prefetch G(kt+1) over S(kt+1)
            CP_WAIT(1);                           // K(kt+1) complete (G may fly)
        }
        __syncthreads();                          // K(kt+1) visible to all
    }

    // ---- l reduce, normalize, write Os[i][q] fp32 ----
    #pragma unroll
    for (int v = 0; v < 4; v++) {
        lsum[v] += __shfl_xor_sync(0xffffffffu, lsum[v], 1);
        lsum[v] += __shfl_xor_sync(0xffffffffu, lsum[v], 2);
    }
    if (lc == 0) {
        #pragma unroll
        for (int mt = 0; mt < 2; mt++) {
            red[wk * 128 + qb + 16 * mt + lr] = lsum[2 * mt];
            red[wk * 128 + qb + 16 * mt + lr + 8] = lsum[2 * mt + 1];
        }
    }
    __syncthreads();
    float inv[4];
    #pragma unroll
    for (int mt = 0; mt < 2; mt++) {
        inv[2 * mt]     = 1.f / (red[qb + 16 * mt + lr]     + red[128 + qb + 16 * mt + lr]);
        inv[2 * mt + 1] = 1.f / (red[qb + 16 * mt + lr + 8] + red[128 + qb + 16 * mt + lr + 8]);
    }
    __syncthreads();
    float* Os = (float*)(smc + O_OS);   // [128 i][132], aliases Q (dead)
    #pragma unroll
    for (int mt = 0; mt < 2; mt++)
        #pragma unroll
        for (int nt = 0; nt < 8; nt++)
            #pragma unroll
            for (int j = 0; j < 4; j++) {
                int q = qb + 16 * mt + lr + 8 * (j >> 1);
                int i = ib + 8 * nt + 2 * lc + (j & 1);
                Os[i * 132 + q] = Ofr[mt][nt][j] * inv[2 * mt + (j >> 1)];
            }
    float* Wt = (float*)(smc + O_WT);   // [128 i][260] = Ww^T, aliases K/G/P (dead)
    #pragma unroll
    for (int j = 0; j < 32; j++) {
        int fl = tid + 256 * j, c = fl >> 5, i4 = (fl & 31) * 4;
        float4 v = *(const float4*)(Ww + (size_t)c * IC + i4);
        Wt[(i4 + 0) * 260 + c] = v.x; Wt[(i4 + 1) * 260 + c] = v.y;
        Wt[(i4 + 2) * 260 + c] = v.z; Wt[(i4 + 3) * 260 + c] = v.w;
    }
    __syncthreads();

    // ---- out[c][q] = Ww Os + b + x (fp32 SIMT) ----
    const int tx = tid & 15, ty = tid >> 4;
    for (int qh = 0; qh < 2; qh++) {
        float acc[16][4];
        #pragma unroll
        for (int cc = 0; cc < 16; cc++)
            acc[cc][0] = acc[cc][1] = acc[cc][2] = acc[cc][3] = 0.f;
        #pragma unroll 4
        for (int i = 0; i < 128; i++) {
            float4 ov = *(const float4*)(Os + i * 132 + qh * 64 + 4 * tx);
            #pragma unroll
            for (int cc = 0; cc < 16; cc++) {
                float w = Wt[i * 260 + ty + 16 * cc];
                acc[cc][0] += w * ov.x; acc[cc][1] += w * ov.y;
                acc[cc][2] += w * ov.z; acc[cc][3] += w * ov.w;
            }
        }
        #pragma unroll
        for (int cc = 0; cc < 16; cc++) {
            int c = ty + 16 * cc;
            float wb = Wb[c];
            size_t base = ((size_t)b * CH + c) * NTOK + q0 + qh * 64 + 4 * tx;
            float4 xr = *(const float4*)(x + base);
            float4 o;
            o.x = acc[cc][0] + wb + xr.x; o.y = acc[cc][1] + wb + xr.y;
            o.z = acc[cc][2] + wb + xr.z; o.w = acc[cc][3] + wb + xr.w;
            *(float4*)(out + base) = o;
        }
    }
}

// ---------------------------------------------------------------------------
extern "C" void kernel_launch(void* const* d_in, const int* in_sizes, int n_in,
                              void* d_out, int out_size)
{
    const float* x    = (const float*)d_in[0];
    const float* g_w  = (const float*)d_in[1];
    const float* g_b  = (const float*)d_in[2];
    const float* th_w = (const float*)d_in[3];
    const float* th_b = (const float*)d_in[4];
    const float* ph_w = (const float*)d_in[5];
    const float* ph_b = (const float*)d_in[6];
    const float* W_w  = (const float*)d_in[7];
    const float* W_b  = (const float*)d_in[8];
    float* out = (float*)d_out;

    const int SMEM1 = (256 * 32 + 384 * 36) * 4;
    cudaFuncSetAttribute(proj_kernel, cudaFuncAttributeMaxDynamicSharedMemorySize, SMEM1);
    cudaFuncSetAttribute(attn_kernel, cudaFuncAttributeMaxDynamicSharedMemorySize, SMEM_ATTN);

    proj_kernel<<<dim3(NTOK / 32, BATCH), 256, SMEM1>>>(
        x, th_w, th_b, ph_w, ph_b, g_w, g_b);
    attn_kernel<<<dim3(NTOK / 128, BATCH), 256, SMEM_ATTN>>>(
        x, W_w, W_b, out);
}

// round 14
// speedup vs baseline: 3.0748x; 1.0265x over previous
#include <cuda_runtime.h>
#include <cuda_bf16.h>
#include <cstdint>
#include <math.h>

#define CH 256
#define IC 128
#define BATCH 8
#define NTOK 4096

// bf16 hi/lo planes. th/ph: [b][n][ic]; g: [b][ic][n].
__device__ __align__(16) __nv_bfloat16 g_th_hi[(size_t)BATCH * NTOK * IC];
__device__ __align__(16) __nv_bfloat16 g_th_lo[(size_t)BATCH * NTOK * IC];
__device__ __align__(16) __nv_bfloat16 g_ph_hi[(size_t)BATCH * NTOK * IC];
__device__ __align__(16) __nv_bfloat16 g_ph_lo[(size_t)BATCH * NTOK * IC];
__device__ __align__(16) __nv_bfloat16 g_g_hi[(size_t)BATCH * NTOK * IC];
__device__ __align__(16) __nv_bfloat16 g_g_lo[(size_t)BATCH * NTOK * IC];

#define CVT2(r, a, b) asm("cvt.rn.satfinite.bf16x2.f32 %0, %1, %2;" : "=r"(r) : "f"(b), "f"(a))
#define CP16(d, s) asm volatile("cp.async.cg.shared.global [%0], [%1], 16;" :: "r"(d), "l"(s) : "memory")
#define CP_COMMIT() asm volatile("cp.async.commit_group;" ::: "memory")
#define CP_WAIT(n) asm volatile("cp.async.wait_group %0;" :: "n"(n) : "memory")
#define LDSM4(r0, r1, r2, r3, a) \
    asm volatile("ldmatrix.sync.aligned.m8n8.x4.shared.b16 {%0,%1,%2,%3}, [%4];" \
        : "=r"(r0), "=r"(r1), "=r"(r2), "=r"(r3) : "r"(a))

__device__ __forceinline__ void mma_bf16(float d[4], uint32_t a0, uint32_t a1,
                                         uint32_t a2, uint32_t a3,
                                         uint32_t b0, uint32_t b1) {
    asm volatile(
        "mma.sync.aligned.m16n8k16.row.col.f32.bf16.bf16.f32 "
        "{%0,%1,%2,%3},{%4,%5,%6,%7},{%8,%9},{%0,%1,%2,%3};"
        : "+f"(d[0]), "+f"(d[1]), "+f"(d[2]), "+f"(d[3])
        : "r"(a0), "r"(a1), "r"(a2), "r"(a3), "r"(b0), "r"(b1));
}

// exp(x) on the FMA pipe (no MUFU): 2^(x*log2e), round trick + deg-5 poly.
__device__ __forceinline__ float fexp(float x) {
    float y = x * 1.44269504089f;
    float z = y + 12582912.0f;               // 1.5*2^23
    int n = __float_as_int(z) - 0x4B400000;
    float f = y - (z - 12582912.0f);         // f in [-0.5, 0.5]
    float p = 1.33336e-3f;
    p = fmaf(p, f, 9.61813e-3f);
    p = fmaf(p, f, 5.550411e-2f);
    p = fmaf(p, f, 2.4022651e-1f);
    p = fmaf(p, f, 6.9314718e-1f);
    p = fmaf(p, f, 1.0f);
    return __int_as_float(__float_as_int(p) + (n << 23));
}

// ---------------------------------------------------------------------------
// Kernel 1: fp32 projections -> bf16 hi/lo planes (smem transpose for stores)
// ---------------------------------------------------------------------------
__global__ void proj_kernel(const float* __restrict__ x,
                            const float* __restrict__ th_w, const float* __restrict__ th_b,
                            const float* __restrict__ ph_w, const float* __restrict__ ph_b,
                            const float* __restrict__ g_w,  const float* __restrict__ g_b)
{
    extern __shared__ float sm1[];
    float* Xs = sm1;              // [256][32]
    float* Ws = sm1 + 8192;       // [384][36]
    const int b = blockIdx.y, n0 = blockIdx.x * 32, tid = threadIdx.x;
    const int tx = tid & 7, ty = tid >> 3;

    const float* xb = x + (size_t)b * CH * NTOK;
    #pragma unroll
    for (int j = 0; j < 8; j++) {
        int fl = tid + 256 * j, c = fl >> 3, u = fl & 7;
        *(float4*)(Xs + c * 32 + 4 * u) = *(const float4*)(xb + (size_t)c * NTOK + n0 + 4 * u);
    }
    float acc[12][4];
    #pragma unroll
    for (int m = 0; m < 12; m++) {
        int r = ty + 32 * m;
        float bias = (r < 128) ? th_b[r] : (r < 256 ? ph_b[r - 128] : g_b[r - 256]);
        acc[m][0] = acc[m][1] = acc[m][2] = acc[m][3] = bias;
    }
    for (int c0 = 0; c0 < 256; c0 += 32) {
        __syncthreads();
        #pragma unroll
        for (int j = 0; j < 12; j++) {
            int fl = tid + 256 * j, r = fl >> 3, u = fl & 7;
            const float* ws = (r < 128) ? (th_w + (size_t)r * CH)
                            : (r < 256) ? (ph_w + (size_t)(r - 128) * CH)
                                        : (g_w + (size_t)(r - 256) * CH);
            *(float4*)(Ws + r * 36 + 4 * u) = *(const float4*)(ws + c0 + 4 * u);
        }
        __syncthreads();
        #pragma unroll 8
        for (int c = 0; c < 32; c++) {
            float4 xv = *(const float4*)(Xs + (c0 + c) * 32 + 4 * tx);
            #pragma unroll
            for (int m = 0; m < 12; m++) {
                float w = Ws[(ty + 32 * m) * 36 + c];
                acc[m][0] += w * xv.x; acc[m][1] += w * xv.y;
                acc[m][2] += w * xv.z; acc[m][3] += w * xv.w;
            }
        }
    }
    __syncthreads();
    float* Sm = sm1;   // [384][33]
    #pragma unroll
    for (int m = 0; m < 12; m++) {
        int r = ty + 32 * m;
        #pragma unroll
        for (int j = 0; j < 4; j++) Sm[r * 33 + 4 * tx + j] = acc[m][j];
    }
    __syncthreads();
    const size_t bN = (size_t)b * NTOK;
    #pragma unroll
    for (int it = 0; it < 4; it++) {   // theta/phi: [n][ic] rows
        int idx = tid + 256 * it;
        int t = idx >> 9, rem = idx & 511, n = rem >> 4, seg = rem & 15;
        uint32_t hp[4], lp[4];
        #pragma unroll
        for (int j = 0; j < 4; j++) {
            float a = Sm[(t * 128 + seg * 8 + 2 * j) * 33 + n];
            float c = Sm[(t * 128 + seg * 8 + 2 * j + 1) * 33 + n];
            __nv_bfloat16 ha = __float2bfloat16(a), hc = __float2bfloat16(c);
            CVT2(hp[j], a, c);
            CVT2(lp[j], a - __bfloat162float(ha), c - __bfloat162float(hc));
        }
        __nv_bfloat16* hi = t ? g_ph_hi : g_th_hi;
        __nv_bfloat16* lo = t ? g_ph_lo : g_th_lo;
        size_t base = (bN + n0 + n) * IC + seg * 8;
        *(uint4*)(hi + base) = make_uint4(hp[0], hp[1], hp[2], hp[3]);
        *(uint4*)(lo + base) = make_uint4(lp[0], lp[1], lp[2], lp[3]);
    }
    #pragma unroll
    for (int it = 0; it < 2; it++) {   // g transposed: [ic][n]
        int idx = tid + 256 * it, ic = idx >> 2, ch = idx & 3;
        uint32_t hp[4], lp[4];
        #pragma unroll
        for (int j = 0; j < 4; j++) {
            float a = Sm[(256 + ic) * 33 + ch * 8 + 2 * j];
            float c = Sm[(256 + ic) * 33 + ch * 8 + 2 * j + 1];
            __nv_bfloat16 ha = __float2bfloat16(a), hc = __float2bfloat16(c);
            CVT2(hp[j], a, c);
            CVT2(lp[j], a - __bfloat162float(ha), c - __bfloat162float(hc));
        }
        size_t base = ((size_t)b * IC + ic) * NTOK + n0 + ch * 8;
        *(uint4*)(g_g_hi + base) = make_uint4(hp[0], hp[1], hp[2], hp[3]);
        *(uint4*)(g_g_lo + base) = make_uint4(lp[0], lp[1], lp[2], lp[3]);
    }
}

// ---------------------------------------------------------------------------
// Kernel 2: mma.sync flash attention, register-resident P, cp.async pipeline,
// + fused out-proj. 256 thr, grid (32,8). Warp w owns q rows [16w,16w+16),
// ALL 64 keys per tile: softmax + P conversion stay in registers.
// ---------------------------------------------------------------------------
#define O_QHI 0
#define O_QLO 34816
#define O_KHI 69632
#define O_KLO 87040
#define O_GHI 104448
#define O_GLO 122880
#define O_OS 0
#define O_WT 69632
#define SMEM_ATTN 203776

__global__ void __launch_bounds__(256, 1)
attn_kernel(const float* __restrict__ x, const float* __restrict__ Ww,
            const float* __restrict__ Wb, float* __restrict__ out)
{
    extern __shared__ char smc[];
    const int b = blockIdx.y, q0 = blockIdx.x * 128, tid = threadIdx.x;
    const int lane = tid & 31, wid = tid >> 5;
    const int lr = lane >> 2, lc = lane & 3;
    const int qw = 16 * wid;                 // warp's q-row base
    const size_t bN = (size_t)b * NTOK;
    const uint32_t smb = (uint32_t)__cvta_generic_to_shared(smc);

    // ldmatrix row/col selectors
    const int arow = (lane & 7) + ((lane >> 3) & 1) * 8;  // A-type x4
    const int acol = (lane >> 4) * 16;
    const int brow = (lane & 7) + (lane >> 4) * 8;        // B-type x4 (2 n8 per ldsm)
    const int bcol = ((lane >> 3) & 1) * 16;

    auto issue_K = [&](int kt) {
        const int k0 = kt * 64;
        #pragma unroll
        for (int j = 0; j < 8; j++) {
            int idx = tid + 256 * j;
            int plane = idx >> 10, e = idx & 1023, row = e >> 4, seg = e & 15;
            const __nv_bfloat16* src = (plane ? g_ph_lo : g_ph_hi) + (bN + k0 + row) * IC + seg * 8;
            uint32_t dst = smb + (plane ? O_KLO : O_KHI) + row * 272 + seg * 16;
            CP16(dst, src);
        }
        CP_COMMIT();
    };
    auto issue_G = [&](int kt) {
        const int k0 = kt * 64;
        #pragma unroll
        for (int j = 0; j < 8; j++) {
            int idx = tid + 256 * j;
            int plane = idx >> 10, e = idx & 1023, row = e >> 3, seg = e & 7;
            const __nv_bfloat16* src = (plane ? g_g_lo : g_g_hi) + ((size_t)b * IC + row) * NTOK + k0 + seg * 8;
            uint32_t dst = smb + (plane ? O_GLO : O_GHI) + row * 144 + seg * 16;
            CP16(dst, src);
        }
        CP_COMMIT();
    };

    // ---- Q tile -> smem (hi/lo), padded rows 272B ----
    #pragma unroll
    for (int j = 0; j < 16; j++) {
        int idx = tid + 256 * j;
        int plane = idx >> 11, e = idx & 2047, row = e >> 4, seg = e & 15;
        const __nv_bfloat16* src = (plane ? g_th_lo : g_th_hi) + (bN + q0 + row) * IC + seg * 8;
        *(uint4*)(smc + (plane ? O_QLO : O_QHI) + row * 272 + seg * 16) = *(const uint4*)src;
    }
    issue_K(0);
    issue_G(0);
    CP_WAIT(0);
    __syncthreads();

    float Ofr[16][4] = {};
    float ls0 = 0.f, ls1 = 0.f;
    float M0 = 0.f, M1 = 0.f;

    for (int kt = 0; kt < NTOK / 64; kt++) {
        // ---- S = Q K^T (warp: q16 x all 64 keys), 3-term bf16 split ----
        float S[8][4] = {};
        #pragma unroll
        for (int ks = 0; ks < 8; ks++) {
            uint32_t ah[4], al[4];
            uint32_t ab = (uint32_t)((qw + arow) * 272 + 32 * ks + acol);
            LDSM4(ah[0], ah[1], ah[2], ah[3], smb + O_QHI + ab);
            LDSM4(al[0], al[1], al[2], al[3], smb + O_QLO + ab);
            #pragma unroll
            for (int np = 0; np < 4; np++) {
                uint32_t bb = (uint32_t)((16 * np + brow) * 272 + 32 * ks + bcol);
                uint32_t bh[4], bl[4];
                LDSM4(bh[0], bh[1], bh[2], bh[3], smb + O_KHI + bb);
                LDSM4(bl[0], bl[1], bl[2], bl[3], smb + O_KLO + bb);
                #pragma unroll
                for (int h = 0; h < 2; h++) {
                    mma_bf16(S[2 * np + h], ah[0], ah[1], ah[2], ah[3], bh[2 * h], bh[2 * h + 1]);
                    mma_bf16(S[2 * np + h], ah[0], ah[1], ah[2], ah[3], bl[2 * h], bl[2 * h + 1]);
                    mma_bf16(S[2 * np + h], al[0], al[1], al[2], al[3], bh[2 * h], bh[2 * h + 1]);
                }
            }
        }
        CP_WAIT(0);                 // G(kt) complete (pending: only G(kt) here)
        __syncthreads();            // all done reading K(kt); G(kt) visible
        if (kt < NTOK / 64 - 1) issue_K(kt + 1);   // K(kt+1) over softmax+PV

        if (kt == 0) {   // fixed reference max from tile 0 (warp-local rows)
            float m0 = -1e30f, m1 = -1e30f;
            #pragma unroll
            for (int nt = 0; nt < 8; nt++) {
                m0 = fmaxf(m0, fmaxf(S[nt][0], S[nt][1]));
                m1 = fmaxf(m1, fmaxf(S[nt][2], S[nt][3]));
            }
            m0 = fmaxf(m0, __shfl_xor_sync(0xffffffffu, m0, 1));
            m0 = fmaxf(m0, __shfl_xor_sync(0xffffffffu, m0, 2));
            m1 = fmaxf(m1, __shfl_xor_sync(0xffffffffu, m1, 1));
            m1 = fmaxf(m1, __shfl_xor_sync(0xffffffffu, m1, 2));
            M0 = m0; M1 = m1;
        }

        // ---- P = exp(S - M) -> bf16 hi/lo A-fragments, in registers ----
        uint32_t Pa_h[4][4], Pa_l[4][4];
        #pragma unroll
        for (int j = 0; j < 4; j++) {
            #pragma unroll
            for (int h = 0; h < 2; h++) {
                const float* sv = S[2 * j + h];
                float e0 = fexp(sv[0] - M0), e1 = fexp(sv[1] - M0);
                float e2 = fexp(sv[2] - M1), e3 = fexp(sv[3] - M1);
                ls0 += e0 + e1; ls1 += e2 + e3;
                __nv_bfloat16 c0 = __float2bfloat16(e0), c1 = __float2bfloat16(e1);
                __nv_bfloat16 c2 = __float2bfloat16(e2), c3 = __float2bfloat16(e3);
                CVT2(Pa_h[j][2 * h], e0, e1);
                CVT2(Pa_h[j][2 * h + 1], e2, e3);
                CVT2(Pa_l[j][2 * h], e0 - __bfloat162float(c0), e1 - __bfloat162float(c1));
                CVT2(Pa_l[j][2 * h + 1], e2 - __bfloat162float(c2), e3 - __bfloat162float(c3));
            }
        }

        // ---- O += P G^T (warp: q16 x all 128 i), 3-term, no barrier ----
        #pragma unroll
        for (int j = 0; j < 4; j++) {
            #pragma unroll
            for (int np = 0; np < 8; np++) {
                uint32_t gb = (uint32_t)((16 * np + brow) * 144 + 32 * j + bcol);
                uint32_t gh[4], gl[4];
                LDSM4(gh[0], gh[1], gh[2], gh[3], smb + O_GHI + gb);
                LDSM4(gl[0], gl[1], gl[2], gl[3], smb + O_GLO + gb);
                #pragma unroll
                for (int h = 0; h < 2; h++) {
                    mma_bf16(Ofr[2 * np + h], Pa_h[j][0], Pa_h[j][1], Pa_h[j][2], Pa_h[j][3],
                             gh[2 * h], gh[2 * h + 1]);
                    mma_bf16(Ofr[2 * np + h], Pa_h[j][0], Pa_h[j][1], Pa_h[j][2], Pa_h[j][3],
                             gl[2 * h], gl[2 * h + 1]);
                    mma_bf16(Ofr[2 * np + h], Pa_l[j][0], Pa_l[j][1], Pa_l[j][2], Pa_l[j][3],
                             gh[2 * h], gh[2 * h + 1]);
                }
            }
        }
        __syncthreads();                          // all done reading G(kt)
        if (kt < NTOK / 64 - 1) {
            issue_G(kt + 1);                      // G(kt+1) over S(kt+1)
            CP_WAIT(1);                           // K(kt+1) complete
        }
        __syncthreads();                          // K(kt+1) visible to all
    }

    // ---- l reduce (warp-local rows), normalize, write Os[i][q] fp32 ----
    ls0 += __shfl_xor_sync(0xffffffffu, ls0, 1);
    ls0 += __shfl_xor_sync(0xffffffffu, ls0, 2);
    ls1 += __shfl_xor_sync(0xffffffffu, ls1, 1);
    ls1 += __shfl_xor_sync(0xffffffffu, ls1, 2);
    float inv0 = 1.f / ls0, inv1 = 1.f / ls1;

    float* Os = (float*)(smc + O_OS);   // [128 i][132], aliases Q (dead)
    #pragma unroll
    for (int nt = 0; nt < 16; nt++)
        #pragma unroll
        for (int j = 0; j < 4; j++) {
            int q = qw + lr + 8 * (j >> 1);
            int i = 8 * nt + 2 * lc + (j & 1);
            Os[i * 132 + q] = Ofr[nt][j] * ((j >> 1) ? inv1 : inv0);
        }
    float* Wt = (float*)(smc + O_WT);   // [128 i][260] = Ww^T, aliases K/G (dead)
    #pragma unroll
    for (int j = 0; j < 32; j++) {
        int fl = tid + 256 * j, c = fl >> 5, i4 = (fl & 31) * 4;
        float4 v = *(const float4*)(Ww + (size_t)c * IC + i4);
        Wt[(i4 + 0) * 260 + c] = v.x; Wt[(i4 + 1) * 260 + c] = v.y;
        Wt[(i4 + 2) * 260 + c] = v.z; Wt[(i4 + 3) * 260 + c] = v.w;
    }
    __syncthreads();

    // ---- out[c][q] = Ww Os + b + x (fp32 SIMT) ----
    const int tx = tid & 15, ty = tid >> 4;
    for (int qh = 0; qh < 2; qh++) {
        float acc[16][4];
        #pragma unroll
        for (int cc = 0; cc < 16; cc++)
            acc[cc][0] = acc[cc][1] = acc[cc][2] = acc[cc][3] = 0.f;
        #pragma unroll 4
        for (int i = 0; i < 128; i++) {
            float4 ov = *(const float4*)(Os + i * 132 + qh * 64 + 4 * tx);
            #pragma unroll
            for (int cc = 0; cc < 16; cc++) {
                float w = Wt[i * 260 + ty + 16 * cc];
                acc[cc][0] += w * ov.x; acc[cc][1] += w * ov.y;
                acc[cc][2] += w * ov.z; acc[cc][3] += w * ov.w;
            }
        }
        #pragma unroll
        for (int cc = 0; cc < 16; cc++) {
            int c = ty + 16 * cc;
            float wb = Wb[c];
            size_t base = ((size_t)b * CH + c) * NTOK + q0 + qh * 64 + 4 * tx;
            float4 xr = *(const float4*)(x + base);
            float4 o;
            o.x = acc[cc][0] + wb + xr.x; o.y = acc[cc][1] + wb + xr.y;
            o.z = acc[cc][2] + wb + xr.z; o.w = acc[cc][3] + wb + xr.w;
            *(float4*)(out + base) = o;
        }
    }
}

// ---------------------------------------------------------------------------
extern "C" void kernel_launch(void* const* d_in, const int* in_sizes, int n_in,
                              void* d_out, int out_size)
{
    const float* x    = (const float*)d_in[0];
    const float* g_w  = (const float*)d_in[1];
    const float* g_b  = (const float*)d_in[2];
    const float* th_w = (const float*)d_in[3];
    const float* th_b = (const float*)d_in[4];
    const float* ph_w = (const float*)d_in[5];
    const float* ph_b = (const float*)d_in[6];
    const float* W_w  = (const float*)d_in[7];
    const float* W_b  = (const float*)d_in[8];
    float* out = (float*)d_out;

    const int SMEM1 = (256 * 32 + 384 * 36) * 4;
    cudaFuncSetAttribute(proj_kernel, cudaFuncAttributeMaxDynamicSharedMemorySize, SMEM1);
    cudaFuncSetAttribute(attn_kernel, cudaFuncAttributeMaxDynamicSharedMemorySize, SMEM_ATTN);

    proj_kernel<<<dim3(NTOK / 32, BATCH), 256, SMEM1>>>(
        x, th_w, th_b, ph_w, ph_b, g_w, g_b);
    attn_kernel<<<dim3(NTOK / 128, BATCH), 256, SMEM_ATTN>>>(
        x, W_w, W_b, out);
}

// round 15
// speedup vs baseline: 3.4481x; 1.1214x over previous
#include <cuda_runtime.h>
#include <cuda_bf16.h>
#include <cstdint>
#include <math.h>

#define CH 256
#define IC 128
#define BATCH 8
#define NTOK 4096

// bf16 hi/lo planes. th/ph: [b][n][ic]; g: [b][ic][n]; x: [b][n][c]; w: [384][256].
__device__ __align__(16) __nv_bfloat16 g_th_hi[(size_t)BATCH * NTOK * IC];
__device__ __align__(16) __nv_bfloat16 g_th_lo[(size_t)BATCH * NTOK * IC];
__device__ __align__(16) __nv_bfloat16 g_ph_hi[(size_t)BATCH * NTOK * IC];
__device__ __align__(16) __nv_bfloat16 g_ph_lo[(size_t)BATCH * NTOK * IC];
__device__ __align__(16) __nv_bfloat16 g_g_hi[(size_t)BATCH * NTOK * IC];
__device__ __align__(16) __nv_bfloat16 g_g_lo[(size_t)BATCH * NTOK * IC];
__device__ __align__(16) __nv_bfloat16 gx_hi[(size_t)BATCH * NTOK * CH];
__device__ __align__(16) __nv_bfloat16 gx_lo[(size_t)BATCH * NTOK * CH];
__device__ __align__(16) __nv_bfloat16 gw_hi[384 * 256];
__device__ __align__(16) __nv_bfloat16 gw_lo[384 * 256];
__device__ float gbias[384];

#define CVT2(r, a, b) asm("cvt.rn.satfinite.bf16x2.f32 %0, %1, %2;" : "=r"(r) : "f"(b), "f"(a))
#define CP16(d, s) asm volatile("cp.async.cg.shared.global [%0], [%1], 16;" :: "r"(d), "l"(s) : "memory")
#define CP_COMMIT() asm volatile("cp.async.commit_group;" ::: "memory")
#define CP_WAIT(n) asm volatile("cp.async.wait_group %0;" :: "n"(n) : "memory")
#define LDSM4(r0, r1, r2, r3, a) \
    asm volatile("ldmatrix.sync.aligned.m8n8.x4.shared.b16 {%0,%1,%2,%3}, [%4];" \
        : "=r"(r0), "=r"(r1), "=r"(r2), "=r"(r3) : "r"(a))

__device__ __forceinline__ void mma_bf16(float d[4], uint32_t a0, uint32_t a1,
                                         uint32_t a2, uint32_t a3,
                                         uint32_t b0, uint32_t b1) {
    asm volatile(
        "mma.sync.aligned.m16n8k16.row.col.f32.bf16.bf16.f32 "
        "{%0,%1,%2,%3},{%4,%5,%6,%7},{%8,%9},{%0,%1,%2,%3};"
        : "+f"(d[0]), "+f"(d[1]), "+f"(d[2]), "+f"(d[3])
        : "r"(a0), "r"(a1), "r"(a2), "r"(a3), "r"(b0), "r"(b1));
}

// exp(x) on the FMA pipe (no MUFU): 2^(x*log2e), round trick + deg-5 poly.
__device__ __forceinline__ float fexp(float x) {
    float y = x * 1.44269504089f;
    float z = y + 12582912.0f;               // 1.5*2^23
    int n = __float_as_int(z) - 0x4B400000;
    float f = y - (z - 12582912.0f);         // f in [-0.5, 0.5]
    float p = 1.33336e-3f;
    p = fmaf(p, f, 9.61813e-3f);
    p = fmaf(p, f, 5.550411e-2f);
    p = fmaf(p, f, 2.4022651e-1f);
    p = fmaf(p, f, 6.9314718e-1f);
    p = fmaf(p, f, 1.0f);
    return __int_as_float(__float_as_int(p) + (n << 23));
}

__device__ __forceinline__ void split2(float a, float c, uint32_t& h, uint32_t& l) {
    __nv_bfloat16 ha = __float2bfloat16(a), hc = __float2bfloat16(c);
    CVT2(h, a, c);
    CVT2(l, a - __bfloat162float(ha), c - __bfloat162float(hc));
}

// ---------------------------------------------------------------------------
// Kernel 0a: weights + biases -> bf16 hi/lo planes. rows: 0-127 th, 128-255 ph,
// 256-383 g. grid 96 x 256 thr.
// ---------------------------------------------------------------------------
__global__ void convert_w(const float* __restrict__ th_w, const float* __restrict__ th_b,
                          const float* __restrict__ ph_w, const float* __restrict__ ph_b,
                          const float* __restrict__ g_w,  const float* __restrict__ g_b)
{
    int g = blockIdx.x * 256 + threadIdx.x;
    #pragma unroll
    for (int j = 0; j < 2; j++) {
        int p = g + j * 24576;               // pair index, 49152 total
        int r = p >> 7, cp = p & 127, c = 2 * cp;
        const float* src = (r < 128) ? (th_w + (size_t)r * CH)
                         : (r < 256) ? (ph_w + (size_t)(r - 128) * CH)
                                     : (g_w + (size_t)(r - 256) * CH);
        uint32_t h, l;
        split2(src[c], src[c + 1], h, l);
        ((uint32_t*)gw_hi)[p] = h;
        ((uint32_t*)gw_lo)[p] = l;
    }
    if (g < 384)
        gbias[g] = (g < 128) ? th_b[g] : (g < 256 ? ph_b[g - 128] : g_b[g - 256]);
}

// ---------------------------------------------------------------------------
// Kernel 0b: x [b][c][n] fp32 -> gx hi/lo [b][n][c] bf16 (smem transpose).
// grid (256, 8): blockIdx.x = ct*64 + ntile. 256 thr.
// ---------------------------------------------------------------------------
__global__ void convert_x(const float* __restrict__ x)
{
    __shared__ float Xs[64 * 65];
    const int b = blockIdx.y, ct = blockIdx.x >> 6, nt = blockIdx.x & 63;
    const int c0 = ct * 64, n0 = nt * 64, tid = threadIdx.x;
    #pragma unroll
    for (int j = 0; j < 4; j++) {
        int fl = tid + 256 * j;              // 1024 float4 tasks
        int c = fl >> 4, ns = fl & 15;
        float4 v = *(const float4*)(x + ((size_t)b * CH + c0 + c) * NTOK + n0 + 4 * ns);
        Xs[c * 65 + 4 * ns + 0] = v.x; Xs[c * 65 + 4 * ns + 1] = v.y;
        Xs[c * 65 + 4 * ns + 2] = v.z; Xs[c * 65 + 4 * ns + 3] = v.w;
    }
    __syncthreads();
    #pragma unroll
    for (int j = 0; j < 8; j++) {
        int t = tid + 256 * j;               // 2048 tasks: n x cpair
        int n = t >> 5, cp = t & 31;
        uint32_t h, l;
        split2(Xs[(2 * cp) * 65 + n], Xs[(2 * cp + 1) * 65 + n], h, l);
        size_t base = ((size_t)b * NTOK + n0 + n) * CH + c0;
        ((uint32_t*)(gx_hi + base))[cp] = h;
        ((uint32_t*)(gx_lo + base))[cp] = l;
    }
}

// ---------------------------------------------------------------------------
// Kernel 1: mma projections. grid (64, 8), 256 thr (8 warps: 4 n-tiles x 2
// r-halves). Per block: 64 n x 384 r, K=256 in 8 chunks of 32c, W dbl-buffered.
// ---------------------------------------------------------------------------
#define P_XHI 0
#define P_XLO 33792
#define P_WS  67584
#define P_ST  67584
#define SMEM_PROJ 190464

__global__ void __launch_bounds__(256, 1) proj_kernel()
{
    extern __shared__ char smc[];
    const int b = blockIdx.y, nb = blockIdx.x * 64, tid = threadIdx.x;
    const int lane = tid & 31, wid = tid >> 5;
    const int m0 = 16 * (wid & 3), rh = 192 * (wid >> 2);
    const int lr = lane >> 2, lc = lane & 3;
    const size_t bN = (size_t)b * NTOK;
    const uint32_t smb = (uint32_t)__cvta_generic_to_shared(smc);

    const int arow = (lane & 7) + ((lane >> 3) & 1) * 8;
    const int acol = (lane >> 4) * 16;
    const int brow = (lane & 7) + (lane >> 4) * 8;
    const int bcol = ((lane >> 3) & 1) * 16;

    // X tile: 64 rows x 512B x 2 planes
    #pragma unroll
    for (int j = 0; j < 16; j++) {
        int idx = tid + 256 * j;
        int plane = idx >> 11, e = idx & 2047, row = e >> 5, seg = e & 31;
        const __nv_bfloat16* src = (plane ? gx_lo : gx_hi) + (bN + nb + row) * CH + seg * 8;
        CP16(smb + (plane ? P_XLO : P_XHI) + row * 528 + seg * 16, src);
    }
    CP_COMMIT();
    auto issue_W = [&](int ck, int buf) {
        #pragma unroll
        for (int j = 0; j < 12; j++) {
            int idx = tid + 256 * j;
            int plane = j >= 6, e = idx - plane * 1536, row = e >> 2, seg = e & 3;
            const __nv_bfloat16* src = (plane ? gw_lo : gw_hi) + row * 256 + ck * 32 + seg * 8;
            CP16(smb + P_WS + buf * 61440 + plane * 30720 + row * 80 + seg * 16, src);
        }
        CP_COMMIT();
    };
    issue_W(0, 0);

    float acc[24][4] = {};
    for (int ck = 0; ck < 8; ck++) {
        CP_WAIT(0);
        __syncthreads();
        if (ck < 7) issue_W(ck + 1, (ck + 1) & 1);
        uint32_t wb = smb + P_WS + (ck & 1) * 61440;
        #pragma unroll
        for (int ks = 0; ks < 2; ks++) {
            uint32_t ah[4], al[4];
            uint32_t ab = (uint32_t)((m0 + arow) * 528 + ck * 64 + ks * 32 + acol);
            LDSM4(ah[0], ah[1], ah[2], ah[3], smb + P_XHI + ab);
            LDSM4(al[0], al[1], al[2], al[3], smb + P_XLO + ab);
            #pragma unroll
            for (int rg = 0; rg < 12; rg++) {
                uint32_t bb = wb + (uint32_t)((rh + 16 * rg + brow) * 80 + ks * 32 + bcol);
                uint32_t bh[4], bl[4];
                LDSM4(bh[0], bh[1], bh[2], bh[3], bb);
                LDSM4(bl[0], bl[1], bl[2], bl[3], bb + 30720);
                #pragma unroll
                for (int h = 0; h < 2; h++) {
                    mma_bf16(acc[2 * rg + h], ah[0], ah[1], ah[2], ah[3], bh[2 * h], bh[2 * h + 1]);
                    mma_bf16(acc[2 * rg + h], ah[0], ah[1], ah[2], ah[3], bl[2 * h], bl[2 * h + 1]);
                    mma_bf16(acc[2 * rg + h], al[0], al[1], al[2], al[3], bh[2 * h], bh[2 * h + 1]);
                }
            }
        }
    }
    __syncthreads();

    // stage D + bias into Sm[64 n][392]
    float* Sm = (float*)(smc + P_ST);
    #pragma unroll
    for (int t = 0; t < 24; t++) {
        int rbase = rh + 8 * t;
        #pragma unroll
        for (int h = 0; h < 2; h++) {
            int n = m0 + lr + 8 * h;
            #pragma unroll
            for (int e = 0; e < 2; e++) {
                int r = rbase + 2 * lc + e;
                Sm[n * 392 + r] = acc[t][2 * h + e] + __ldg(&gbias[r]);
            }
        }
    }
    __syncthreads();

    // th/ph: [b][n][ic] stores
    #pragma unroll
    for (int j = 0; j < 8; j++) {
        int idx = tid + 256 * j;             // 2048: (t, n, seg)
        int t = idx >> 10, rem = idx & 1023, n = rem >> 4, seg = rem & 15;
        const float* row = Sm + n * 392 + t * 128 + seg * 8;
        uint32_t hp[4], lp[4];
        #pragma unroll
        for (int q = 0; q < 4; q++) split2(row[2 * q], row[2 * q + 1], hp[q], lp[q]);
        __nv_bfloat16* hi = t ? g_ph_hi : g_th_hi;
        __nv_bfloat16* lo = t ? g_ph_lo : g_th_lo;
        size_t base = (bN + nb + n) * IC + seg * 8;
        *(uint4*)(hi + base) = make_uint4(hp[0], hp[1], hp[2], hp[3]);
        *(uint4*)(lo + base) = make_uint4(lp[0], lp[1], lp[2], lp[3]);
    }
    // g: [b][ic][n] stores
    #pragma unroll
    for (int j = 0; j < 4; j++) {
        int idx = tid + 256 * j;             // 1024: (ic, nseg)
        int ic = idx >> 3, ns = idx & 7;
        uint32_t hp[4], lp[4];
        #pragma unroll
        for (int q = 0; q < 4; q++)
            split2(Sm[(ns * 8 + 2 * q) * 392 + 256 + ic],
                   Sm[(ns * 8 + 2 * q + 1) * 392 + 256 + ic], hp[q], lp[q]);
        size_t base = ((size_t)b * IC + ic) * NTOK + nb + ns * 8;
        *(uint4*)(g_g_hi + base) = make_uint4(hp[0], hp[1], hp[2], hp[3]);
        *(uint4*)(g_g_lo + base) = make_uint4(lp[0], lp[1], lp[2], lp[3]);
    }
}

// ---------------------------------------------------------------------------
// Kernel 2: mma.sync flash attention (register-resident P, cp.async pipeline)
// + fused out-proj. 256 thr, grid (32,8). UNCHANGED from passing R14 kernel.
// ---------------------------------------------------------------------------
#define O_QHI 0
#define O_QLO 34816
#define O_KHI 69632
#define O_KLO 87040
#define O_GHI 104448
#define O_GLO 122880
#define O_OS 0
#define O_WT 69632
#define SMEM_ATTN 203776

__global__ void __launch_bounds__(256, 1)
attn_kernel(const float* __restrict__ x, const float* __restrict__ Ww,
            const float* __restrict__ Wb, float* __restrict__ out)
{
    extern __shared__ char smc[];
    const int b = blockIdx.y, q0 = blockIdx.x * 128, tid = threadIdx.x;
    const int lane = tid & 31, wid = tid >> 5;
    const int lr = lane >> 2, lc = lane & 3;
    const int qw = 16 * wid;
    const size_t bN = (size_t)b * NTOK;
    const uint32_t smb = (uint32_t)__cvta_generic_to_shared(smc);

    const int arow = (lane & 7) + ((lane >> 3) & 1) * 8;
    const int acol = (lane >> 4) * 16;
    const int brow = (lane & 7) + (lane >> 4) * 8;
    const int bcol = ((lane >> 3) & 1) * 16;

    auto issue_K = [&](int kt) {
        const int k0 = kt * 64;
        #pragma unroll
        for (int j = 0; j < 8; j++) {
            int idx = tid + 256 * j;
            int plane = idx >> 10, e = idx & 1023, row = e >> 4, seg = e & 15;
            const __nv_bfloat16* src = (plane ? g_ph_lo : g_ph_hi) + (bN + k0 + row) * IC + seg * 8;
            CP16(smb + (plane ? O_KLO : O_KHI) + row * 272 + seg * 16, src);
        }
        CP_COMMIT();
    };
    auto issue_G = [&](int kt) {
        const int k0 = kt * 64;
        #pragma unroll
        for (int j = 0; j < 8; j++) {
            int idx = tid + 256 * j;
            int plane = idx >> 10, e = idx & 1023, row = e >> 3, seg = e & 7;
            const __nv_bfloat16* src = (plane ? g_g_lo : g_g_hi) + ((size_t)b * IC + row) * NTOK + k0 + seg * 8;
            CP16(smb + (plane ? O_GLO : O_GHI) + row * 144 + seg * 16, src);
        }
        CP_COMMIT();
    };

    #pragma unroll
    for (int j = 0; j < 16; j++) {
        int idx = tid + 256 * j;
        int plane = idx >> 11, e = idx & 2047, row = e >> 4, seg = e & 15;
        const __nv_bfloat16* src = (plane ? g_th_lo : g_th_hi) + (bN + q0 + row) * IC + seg * 8;
        *(uint4*)(smc + (plane ? O_QLO : O_QHI) + row * 272 + seg * 16) = *(const uint4*)src;
    }
    issue_K(0);
    issue_G(0);
    CP_WAIT(0);
    __syncthreads();

    float Ofr[16][4] = {};
    float ls0 = 0.f, ls1 = 0.f;
    float M0 = 0.f, M1 = 0.f;

    for (int kt = 0; kt < NTOK / 64; kt++) {
        float S[8][4] = {};
        #pragma unroll
        for (int ks = 0; ks < 8; ks++) {
            uint32_t ah[4], al[4];
            uint32_t ab = (uint32_t)((qw + arow) * 272 + 32 * ks + acol);
            LDSM4(ah[0], ah[1], ah[2], ah[3], smb + O_QHI + ab);
            LDSM4(al[0], al[1], al[2], al[3], smb + O_QLO + ab);
            #pragma unroll
            for (int np = 0; np < 4; np++) {
                uint32_t bb = (uint32_t)((16 * np + brow) * 272 + 32 * ks + bcol);
                uint32_t bh[4], bl[4];
                LDSM4(bh[0], bh[1], bh[2], bh[3], smb + O_KHI + bb);
                LDSM4(bl[0], bl[1], bl[2], bl[3], smb + O_KLO + bb);
                #pragma unroll
                for (int h = 0; h < 2; h++) {
                    mma_bf16(S[2 * np + h], ah[0], ah[1], ah[2], ah[3], bh[2 * h], bh[2 * h + 1]);
                    mma_bf16(S[2 * np + h], ah[0], ah[1], ah[2], ah[3], bl[2 * h], bl[2 * h + 1]);
                    mma_bf16(S[2 * np + h], al[0], al[1], al[2], al[3], bh[2 * h], bh[2 * h + 1]);
                }
            }
        }
        CP_WAIT(0);
        __syncthreads();
        if (kt < NTOK / 64 - 1) issue_K(kt + 1);

        if (kt == 0) {
            float m0 = -1e30f, m1 = -1e30f;
            #pragma unroll
            for (int nt = 0; nt < 8; nt++) {
                m0 = fmaxf(m0, fmaxf(S[nt][0], S[nt][1]));
                m1 = fmaxf(m1, fmaxf(S[nt][2], S[nt][3]));
            }
            m0 = fmaxf(m0, __shfl_xor_sync(0xffffffffu, m0, 1));
            m0 = fmaxf(m0, __shfl_xor_sync(0xffffffffu, m0, 2));
            m1 = fmaxf(m1, __shfl_xor_sync(0xffffffffu, m1, 1));
            m1 = fmaxf(m1, __shfl_xor_sync(0xffffffffu, m1, 2));
            M0 = m0; M1 = m1;
        }

        uint32_t Pa_h[4][4], Pa_l[4][4];
        #pragma unroll
        for (int j = 0; j < 4; j++) {
            #pragma unroll
            for (int h = 0; h < 2; h++) {
                const float* sv = S[2 * j + h];
                float e0 = fexp(sv[0] - M0), e1 = fexp(sv[1] - M0);
                float e2 = fexp(sv[2] - M1), e3 = fexp(sv[3] - M1);
                ls0 += e0 + e1; ls1 += e2 + e3;
                __nv_bfloat16 c0 = __float2bfloat16(e0), c1 = __float2bfloat16(e1);
                __nv_bfloat16 c2 = __float2bfloat16(e2), c3 = __float2bfloat16(e3);
                CVT2(Pa_h[j][2 * h], e0, e1);
                CVT2(Pa_h[j][2 * h + 1], e2, e3);
                CVT2(Pa_l[j][2 * h], e0 - __bfloat162float(c0), e1 - __bfloat162float(c1));
                CVT2(Pa_l[j][2 * h + 1], e2 - __bfloat162float(c2), e3 - __bfloat162float(c3));
            }
        }

        #pragma unroll
        for (int j = 0; j < 4; j++) {
            #pragma unroll
            for (int np = 0; np < 8; np++) {
                uint32_t gb = (uint32_t)((16 * np + brow) * 144 + 32 * j + bcol);
                uint32_t gh[4], gl[4];
                LDSM4(gh[0], gh[1], gh[2], gh[3], smb + O_GHI + gb);
                LDSM4(gl[0], gl[1], gl[2], gl[3], smb + O_GLO + gb);
                #pragma unroll
                for (int h = 0; h < 2; h++) {
                    mma_bf16(Ofr[2 * np + h], Pa_h[j][0], Pa_h[j][1], Pa_h[j][2], Pa_h[j][3],
                             gh[2 * h], gh[2 * h + 1]);
                    mma_bf16(Ofr[2 * np + h], Pa_h[j][0], Pa_h[j][1], Pa_h[j][2], Pa_h[j][3],
                             gl[2 * h], gl[2 * h + 1]);
                    mma_bf16(Ofr[2 * np + h], Pa_l[j][0], Pa_l[j][1], Pa_l[j][2], Pa_l[j][3],
                             gh[2 * h], gh[2 * h + 1]);
                }
            }
        }
        __syncthreads();
        if (kt < NTOK / 64 - 1) {
            issue_G(kt + 1);
            CP_WAIT(1);
        }
        __syncthreads();
    }

    ls0 += __shfl_xor_sync(0xffffffffu, ls0, 1);
    ls0 += __shfl_xor_sync(0xffffffffu, ls0, 2);
    ls1 += __shfl_xor_sync(0xffffffffu, ls1, 1);
    ls1 += __shfl_xor_sync(0xffffffffu, ls1, 2);
    float inv0 = 1.f / ls0, inv1 = 1.f / ls1;

    float* Os = (float*)(smc + O_OS);
    #pragma unroll
    for (int nt = 0; nt < 16; nt++)
        #pragma unroll
        for (int j = 0; j < 4; j++) {
            int q = qw + lr + 8 * (j >> 1);
            int i = 8 * nt + 2 * lc + (j & 1);
            Os[i * 132 + q] = Ofr[nt][j] * ((j >> 1) ? inv1 : inv0);
        }
    float* Wt = (float*)(smc + O_WT);
    #pragma unroll
    for (int j = 0; j < 32; j++) {
        int fl = tid + 256 * j, c = fl >> 5, i4 = (fl & 31) * 4;
        float4 v = *(const float4*)(Ww + (size_t)c * IC + i4);
        Wt[(i4 + 0) * 260 + c] = v.x; Wt[(i4 + 1) * 260 + c] = v.y;
        Wt[(i4 + 2) * 260 + c] = v.z; Wt[(i4 + 3) * 260 + c] = v.w;
    }
    __syncthreads();

    const int tx = tid & 15, ty = tid >> 4;
    for (int qh = 0; qh < 2; qh++) {
        float acc[16][4];
        #pragma unroll
        for (int cc = 0; cc < 16; cc++)
            acc[cc][0] = acc[cc][1] = acc[cc][2] = acc[cc][3] = 0.f;
        #pragma unroll 4
        for (int i = 0; i < 128; i++) {
            float4 ov = *(const float4*)(Os + i * 132 + qh * 64 + 4 * tx);
            #pragma unroll
            for (int cc = 0; cc < 16; cc++) {
                float w = Wt[i * 260 + ty + 16 * cc];
                acc[cc][0] += w * ov.x; acc[cc][1] += w * ov.y;
                acc[cc][2] += w * ov.z; acc[cc][3] += w * ov.w;
            }
        }
        #pragma unroll
        for (int cc = 0; cc < 16; cc++) {
            int c = ty + 16 * cc;
            float wb = Wb[c];
            size_t base = ((size_t)b * CH + c) * NTOK + q0 + qh * 64 + 4 * tx;
            float4 xr = *(const float4*)(x + base);
            float4 o;
            o.x = acc[cc][0] + wb + xr.x; o.y = acc[cc][1] + wb + xr.y;
            o.z = acc[cc][2] + wb + xr.z; o.w = acc[cc][3] + wb + xr.w;
            *(float4*)(out + base) = o;
        }
    }
}

// ---------------------------------------------------------------------------
extern "C" void kernel_launch(void* const* d_in, const int* in_sizes, int n_in,
                              void* d_out, int out_size)
{
    const float* x    = (const float*)d_in[0];
    const float* g_w  = (const float*)d_in[1];
    const float* g_b  = (const float*)d_in[2];
    const float* th_w = (const float*)d_in[3];
    const float* th_b = (const float*)d_in[4];
    const float* ph_w = (const float*)d_in[5];
    const float* ph_b = (const float*)d_in[6];
    const float* W_w  = (const float*)d_in[7];
    const float* W_b  = (const float*)d_in[8];
    float* out = (float*)d_out;

    cudaFuncSetAttribute(proj_kernel, cudaFuncAttributeMaxDynamicSharedMemorySize, SMEM_PROJ);
    cudaFuncSetAttribute(attn_kernel, cudaFuncAttributeMaxDynamicSharedMemorySize, SMEM_ATTN);

    convert_w<<<96, 256>>>(th_w, th_b, ph_w, ph_b, g_w, g_b);
    convert_x<<<dim3(256, BATCH), 256>>>(x);
    proj_kernel<<<dim3(NTOK / 64, BATCH), 256, SMEM_PROJ>>>();
    attn_kernel<<<dim3(NTOK / 128, BATCH), 256, SMEM_ATTN>>>(
        x, W_w, W_b, out);
}

// round 17
// speedup vs baseline: 3.4492x; 1.0003x over previous
#include <cuda_runtime.h>
#include <cuda_bf16.h>
#include <cstdint>
#include <math.h>

#define CH 256
#define IC 128
#define BATCH 8
#define NTOK 4096

// bf16 hi/lo planes. th/ph: [b][n][ic]; g: [b][ic][n]; x: [b][n][c]; w: [384][256].
__device__ __align__(16) __nv_bfloat16 g_th_hi[(size_t)BATCH * NTOK * IC];
__device__ __align__(16) __nv_bfloat16 g_th_lo[(size_t)BATCH * NTOK * IC];
__device__ __align__(16) __nv_bfloat16 g_ph_hi[(size_t)BATCH * NTOK * IC];
__device__ __align__(16) __nv_bfloat16 g_ph_lo[(size_t)BATCH * NTOK * IC];
__device__ __align__(16) __nv_bfloat16 g_g_hi[(size_t)BATCH * NTOK * IC];
__device__ __align__(16) __nv_bfloat16 g_g_lo[(size_t)BATCH * NTOK * IC];
__device__ __align__(16) __nv_bfloat16 gx_hi[(size_t)BATCH * NTOK * CH];
__device__ __align__(16) __nv_bfloat16 gx_lo[(size_t)BATCH * NTOK * CH];
__device__ __align__(16) __nv_bfloat16 gw_hi[384 * 256];
__device__ __align__(16) __nv_bfloat16 gw_lo[384 * 256];
__device__ float gbias[384];

#define CVT2(r, a, b) asm("cvt.rn.satfinite.bf16x2.f32 %0, %1, %2;" : "=r"(r) : "f"(b), "f"(a))
#define CP16(d, s) asm volatile("cp.async.cg.shared.global [%0], [%1], 16;" :: "r"(d), "l"(s) : "memory")
#define CP_COMMIT() asm volatile("cp.async.commit_group;" ::: "memory")
#define CP_WAIT(n) asm volatile("cp.async.wait_group %0;" :: "n"(n) : "memory")
#define LDSM4(r0, r1, r2, r3, a) \
    asm volatile("ldmatrix.sync.aligned.m8n8.x4.shared.b16 {%0,%1,%2,%3}, [%4];" \
        : "=r"(r0), "=r"(r1), "=r"(r2), "=r"(r3) : "r"(a))

__device__ __forceinline__ void mma_bf16(float d[4], uint32_t a0, uint32_t a1,
                                         uint32_t a2, uint32_t a3,
                                         uint32_t b0, uint32_t b1) {
    asm volatile(
        "mma.sync.aligned.m16n8k16.row.col.f32.bf16.bf16.f32 "
        "{%0,%1,%2,%3},{%4,%5,%6,%7},{%8,%9},{%0,%1,%2,%3};"
        : "+f"(d[0]), "+f"(d[1]), "+f"(d[2]), "+f"(d[3])
        : "r"(a0), "r"(a1), "r"(a2), "r"(a3), "r"(b0), "r"(b1));
}

// exp(x) on the FMA pipe (no MUFU): 2^(x*log2e), round trick + deg-5 poly.
__device__ __forceinline__ float fexp(float x) {
    float y = x * 1.44269504089f;
    float z = y + 12582912.0f;               // 1.5*2^23
    int n = __float_as_int(z) - 0x4B400000;
    float f = y - (z - 12582912.0f);         // f in [-0.5, 0.5]
    float p = 1.33336e-3f;
    p = fmaf(p, f, 9.61813e-3f);
    p = fmaf(p, f, 5.550411e-2f);
    p = fmaf(p, f, 2.4022651e-1f);
    p = fmaf(p, f, 6.9314718e-1f);
    p = fmaf(p, f, 1.0f);
    return __int_as_float(__float_as_int(p) + (n << 23));
}

__device__ __forceinline__ void split2(float a, float c, uint32_t& h, uint32_t& l) {
    __nv_bfloat16 ha = __float2bfloat16(a), hc = __float2bfloat16(c);
    CVT2(h, a, c);
    CVT2(l, a - __bfloat162float(ha), c - __bfloat162float(hc));
}

// ---------------------------------------------------------------------------
// Kernel 0a: weights + biases -> bf16 hi/lo planes.
// ---------------------------------------------------------------------------
__global__ void convert_w(const float* __restrict__ th_w, const float* __restrict__ th_b,
                          const float* __restrict__ ph_w, const float* __restrict__ ph_b,
                          const float* __restrict__ g_w,  const float* __restrict__ g_b)
{
    int g = blockIdx.x * 256 + threadIdx.x;
    #pragma unroll
    for (int j = 0; j < 2; j++) {
        int p = g + j * 24576;
        int r = p >> 7, cp = p & 127, c = 2 * cp;
        const float* src = (r < 128) ? (th_w + (size_t)r * CH)
                         : (r < 256) ? (ph_w + (size_t)(r - 128) * CH)
                                     : (g_w + (size_t)(r - 256) * CH);
        uint32_t h, l;
        split2(src[c], src[c + 1], h, l);
        ((uint32_t*)gw_hi)[p] = h;
        ((uint32_t*)gw_lo)[p] = l;
    }
    if (g < 384)
        gbias[g] = (g < 128) ? th_b[g] : (g < 256 ? ph_b[g - 128] : g_b[g - 256]);
}

// ---------------------------------------------------------------------------
// Kernel 0b: x [b][c][n] fp32 -> gx hi/lo [b][n][c] bf16 (smem transpose).
// ---------------------------------------------------------------------------
__global__ void convert_x(const float* __restrict__ x)
{
    __shared__ float Xs[64 * 65];
    const int b = blockIdx.y, ct = blockIdx.x >> 6, nt = blockIdx.x & 63;
    const int c0 = ct * 64, n0 = nt * 64, tid = threadIdx.x;
    #pragma unroll
    for (int j = 0; j < 4; j++) {
        int fl = tid + 256 * j;
        int c = fl >> 4, ns = fl & 15;
        float4 v = *(const float4*)(x + ((size_t)b * CH + c0 + c) * NTOK + n0 + 4 * ns);
        Xs[c * 65 + 4 * ns + 0] = v.x; Xs[c * 65 + 4 * ns + 1] = v.y;
        Xs[c * 65 + 4 * ns + 2] = v.z; Xs[c * 65 + 4 * ns + 3] = v.w;
    }
    __syncthreads();
    #pragma unroll
    for (int j = 0; j < 8; j++) {
        int t = tid + 256 * j;
        int n = t >> 5, cp = t & 31;
        uint32_t h, l;
        split2(Xs[(2 * cp) * 65 + n], Xs[(2 * cp + 1) * 65 + n], h, l);
        size_t base = ((size_t)b * NTOK + n0 + n) * CH + c0;
        ((uint32_t*)(gx_hi + base))[cp] = h;
        ((uint32_t*)(gx_lo + base))[cp] = l;
    }
}

// ---------------------------------------------------------------------------
// Kernel 1: mma projections (unchanged from R15 passing version).
// ---------------------------------------------------------------------------
#define P_XHI 0
#define P_XLO 33792
#define P_WS  67584
#define P_ST  67584
#define SMEM_PROJ 190464

__global__ void __launch_bounds__(256, 1) proj_kernel()
{
    extern __shared__ char smc[];
    const int b = blockIdx.y, nb = blockIdx.x * 64, tid = threadIdx.x;
    const int lane = tid & 31, wid = tid >> 5;
    const int m0 = 16 * (wid & 3), rh = 192 * (wid >> 2);
    const int lr = lane >> 2, lc = lane & 3;
    const size_t bN = (size_t)b * NTOK;
    const uint32_t smb = (uint32_t)__cvta_generic_to_shared(smc);

    const int arow = (lane & 7) + ((lane >> 3) & 1) * 8;
    const int acol = (lane >> 4) * 16;
    const int brow = (lane & 7) + (lane >> 4) * 8;
    const int bcol = ((lane >> 3) & 1) * 16;

    #pragma unroll
    for (int j = 0; j < 16; j++) {
        int idx = tid + 256 * j;
        int plane = idx >> 11, e = idx & 2047, row = e >> 5, seg = e & 31;
        const __nv_bfloat16* src = (plane ? gx_lo : gx_hi) + (bN + nb + row) * CH + seg * 8;
        CP16(smb + (plane ? P_XLO : P_XHI) + row * 528 + seg * 16, src);
    }
    CP_COMMIT();
    auto issue_W = [&](int ck, int buf) {
        #pragma unroll
        for (int j = 0; j < 12; j++) {
            int idx = tid + 256 * j;
            int plane = j >= 6, e = idx - plane * 1536, row = e >> 2, seg = e & 3;
            const __nv_bfloat16* src = (plane ? gw_lo : gw_hi) + row * 256 + ck * 32 + seg * 8;
            CP16(smb + P_WS + buf * 61440 + plane * 30720 + row * 80 + seg * 16, src);
        }
        CP_COMMIT();
    };
    issue_W(0, 0);

    float acc[24][4] = {};
    for (int ck = 0; ck < 8; ck++) {
        CP_WAIT(0);
        __syncthreads();
        if (ck < 7) issue_W(ck + 1, (ck + 1) & 1);
        uint32_t wb = smb + P_WS + (ck & 1) * 61440;
        #pragma unroll
        for (int ks = 0; ks < 2; ks++) {
            uint32_t ah[4], al[4];
            uint32_t ab = (uint32_t)((m0 + arow) * 528 + ck * 64 + ks * 32 + acol);
            LDSM4(ah[0], ah[1], ah[2], ah[3], smb + P_XHI + ab);
            LDSM4(al[0], al[1], al[2], al[3], smb + P_XLO + ab);
            #pragma unroll
            for (int rg = 0; rg < 12; rg++) {
                uint32_t bb = wb + (uint32_t)((rh + 16 * rg + brow) * 80 + ks * 32 + bcol);
                uint32_t bh[4], bl[4];
                LDSM4(bh[0], bh[1], bh[2], bh[3], bb);
                LDSM4(bl[0], bl[1], bl[2], bl[3], bb + 30720);
                #pragma unroll
                for (int h = 0; h < 2; h++) {
                    mma_bf16(acc[2 * rg + h], ah[0], ah[1], ah[2], ah[3], bh[2 * h], bh[2 * h + 1]);
                    mma_bf16(acc[2 * rg + h], ah[0], ah[1], ah[2], ah[3], bl[2 * h], bl[2 * h + 1]);
                    mma_bf16(acc[2 * rg + h], al[0], al[1], al[2], al[3], bh[2 * h], bh[2 * h + 1]);
                }
            }
        }
    }
    __syncthreads();

    float* Sm = (float*)(smc + P_ST);
    #pragma unroll
    for (int t = 0; t < 24; t++) {
        int rbase = rh + 8 * t;
        #pragma unroll
        for (int h = 0; h < 2; h++) {
            int n = m0 + lr + 8 * h;
            #pragma unroll
            for (int e = 0; e < 2; e++) {
                int r = rbase + 2 * lc + e;
                Sm[n * 392 + r] = acc[t][2 * h + e] + __ldg(&gbias[r]);
            }
        }
    }
    __syncthreads();

    #pragma unroll
    for (int j = 0; j < 8; j++) {
        int idx = tid + 256 * j;
        int t = idx >> 10, rem = idx & 1023, n = rem >> 4, seg = rem & 15;
        const float* row = Sm + n * 392 + t * 128 + seg * 8;
        uint32_t hp[4], lp[4];
        #pragma unroll
        for (int q = 0; q < 4; q++) split2(row[2 * q], row[2 * q + 1], hp[q], lp[q]);
        __nv_bfloat16* hi = t ? g_ph_hi : g_th_hi;
        __nv_bfloat16* lo = t ? g_ph_lo : g_th_lo;
        size_t base = (bN + nb + n) * IC + seg * 8;
        *(uint4*)(hi + base) = make_uint4(hp[0], hp[1], hp[2], hp[3]);
        *(uint4*)(lo + base) = make_uint4(lp[0], lp[1], lp[2], lp[3]);
    }
    #pragma unroll
    for (int j = 0; j < 4; j++) {
        int idx = tid + 256 * j;
        int ic = idx >> 3, ns = idx & 7;
        uint32_t hp[4], lp[4];
        #pragma unroll
        for (int q = 0; q < 4; q++)
            split2(Sm[(ns * 8 + 2 * q) * 392 + 256 + ic],
                   Sm[(ns * 8 + 2 * q + 1) * 392 + 256 + ic], hp[q], lp[q]);
        size_t base = ((size_t)b * IC + ic) * NTOK + nb + ns * 8;
        *(uint4*)(g_g_hi + base) = make_uint4(hp[0], hp[1], hp[2], hp[3]);
        *(uint4*)(g_g_lo + base) = make_uint4(lp[0], lp[1], lp[2], lp[3]);
    }
}

// ---------------------------------------------------------------------------
// Kernel 2: mma.sync flash attention. Q in registers, K+G triple-buffered,
// ONE barrier per tile. 256 thr, grid (32,8). Fused out-proj epilogue.
// Stage layout (71680 B each): KHI +0, KLO +17408, GHI +34816, GLO +53248.
// ---------------------------------------------------------------------------
#define STG 71680
#define O_OS 0
#define O_WT 67584
#define SMEM_ATTN 215040

__global__ void __launch_bounds__(256, 1)
attn_kernel(const float* __restrict__ x, const float* __restrict__ Ww,
            const float* __restrict__ Wb, float* __restrict__ out)
{
    extern __shared__ char smc[];
    const int b = blockIdx.y, q0 = blockIdx.x * 128, tid = threadIdx.x;
    const int lane = tid & 31, wid = tid >> 5;
    const int lr = lane >> 2, lc = lane & 3;
    const int qw = 16 * wid;
    const size_t bN = (size_t)b * NTOK;
    const uint32_t smb = (uint32_t)__cvta_generic_to_shared(smc);

    const int arow = (lane & 7) + ((lane >> 3) & 1) * 8;
    const int acol = (lane >> 4) * 16;
    const int brow = (lane & 7) + (lane >> 4) * 8;
    const int bcol = ((lane >> 3) & 1) * 16;

    // Combined K+G issue for one tile: ONE commit group.
    auto issue = [&](int kt) {
        const uint32_t st = smb + (uint32_t)(kt % 3) * STG;
        const int k0 = kt * 64;
        #pragma unroll
        for (int j = 0; j < 8; j++) {               // K tile [64key][272B] hi/lo
            int idx = tid + 256 * j;
            int plane = idx >> 10, e = idx & 1023, row = e >> 4, seg = e & 15;
            const __nv_bfloat16* src = (plane ? g_ph_lo : g_ph_hi) + (bN + k0 + row) * IC + seg * 8;
            CP16(st + plane * 17408 + row * 272 + seg * 16, src);
        }
        #pragma unroll
        for (int j = 0; j < 8; j++) {               // G tile [128i][144B] hi/lo
            int idx = tid + 256 * j;
            int plane = idx >> 10, e = idx & 1023, row = e >> 3, seg = e & 7;
            const __nv_bfloat16* src = (plane ? g_g_lo : g_g_hi) + ((size_t)b * IC + row) * NTOK + k0 + seg * 8;
            CP16(st + 34816 + plane * 18432 + row * 144 + seg * 16, src);
        }
        CP_COMMIT();
    };

    // ---- prologue: stage Q in smem, hoist fragments to registers ----
    #pragma unroll
    for (int j = 0; j < 16; j++) {
        int idx = tid + 256 * j;
        int plane = idx >> 11, e = idx & 2047, row = e >> 4, seg = e & 15;
        const __nv_bfloat16* src = (plane ? g_th_lo : g_th_hi) + (bN + q0 + row) * IC + seg * 8;
        *(uint4*)(smc + plane * 34816 + row * 272 + seg * 16) = *(const uint4*)src;
    }
    __syncthreads();
    uint32_t Qh[8][4], Ql[8][4];
    #pragma unroll
    for (int ks = 0; ks < 8; ks++) {
        uint32_t ab = (uint32_t)((qw + arow) * 272 + 32 * ks + acol);
        LDSM4(Qh[ks][0], Qh[ks][1], Qh[ks][2], Qh[ks][3], smb + ab);
        LDSM4(Ql[ks][0], Ql[ks][1], Ql[ks][2], Ql[ks][3], smb + 34816 + ab);
    }
    __syncthreads();

    issue(0);
    issue(1);
    CP_WAIT(1);          // tile 0 complete (tile 1 group may fly)
    __syncthreads();

    float Ofr[16][4] = {};
    float ls0 = 0.f, ls1 = 0.f;
    float M0 = 0.f, M1 = 0.f;

    for (int kt = 0; kt < NTOK / 64; kt++) {
        const uint32_t st = smb + (uint32_t)(kt % 3) * STG;

        // ---- S = Q K^T (warp: q16 x all 64 keys), 3-term bf16 split ----
        float S[8][4] = {};
        #pragma unroll
        for (int ks = 0; ks < 8; ks++) {
            #pragma unroll
            for (int np = 0; np < 4; np++) {
                uint32_t bb = st + (uint32_t)((16 * np + brow) * 272 + 32 * ks + bcol);
                uint32_t bh[4], bl[4];
                LDSM4(bh[0], bh[1], bh[2], bh[3], bb);
                LDSM4(bl[0], bl[1], bl[2], bl[3], bb + 17408);
                #pragma unroll
                for (int h = 0; h < 2; h++) {
                    mma_bf16(S[2 * np + h], Qh[ks][0], Qh[ks][1], Qh[ks][2], Qh[ks][3],
                             bh[2 * h], bh[2 * h + 1]);
                    mma_bf16(S[2 * np + h], Qh[ks][0], Qh[ks][1], Qh[ks][2], Qh[ks][3],
                             bl[2 * h], bl[2 * h + 1]);
                    mma_bf16(S[2 * np + h], Ql[ks][0], Ql[ks][1], Ql[ks][2], Ql[ks][3],
                             bh[2 * h], bh[2 * h + 1]);
                }
            }
        }

        if (kt == 0) {   // fixed reference max from tile 0 (warp-local rows)
            float m0 = -1e30f, m1 = -1e30f;
            #pragma unroll
            for (int nt = 0; nt < 8; nt++) {
                m0 = fmaxf(m0, fmaxf(S[nt][0], S[nt][1]));
                m1 = fmaxf(m1, fmaxf(S[nt][2], S[nt][3]));
            }
            m0 = fmaxf(m0, __shfl_xor_sync(0xffffffffu, m0, 1));
            m0 = fmaxf(m0, __shfl_xor_sync(0xffffffffu, m0, 2));
            m1 = fmaxf(m1, __shfl_xor_sync(0xffffffffu, m1, 1));
            m1 = fmaxf(m1, __shfl_xor_sync(0xffffffffu, m1, 2));
            M0 = m0; M1 = m1;
        }

        // ---- P = exp(S - M) -> bf16 hi/lo A-fragments, in registers ----
        uint32_t Pa_h[4][4], Pa_l[4][4];
        #pragma unroll
        for (int j = 0; j < 4; j++) {
            #pragma unroll
            for (int h = 0; h < 2; h++) {
                const float* sv = S[2 * j + h];
                float e0 = fexp(sv[0] - M0), e1 = fexp(sv[1] - M0);
                float e2 = fexp(sv[2] - M1), e3 = fexp(sv[3] - M1);
                ls0 += e0 + e1; ls1 += e2 + e3;
                __nv_bfloat16 c0 = __float2bfloat16(e0), c1 = __float2bfloat16(e1);
                __nv_bfloat16 c2 = __float2bfloat16(e2), c3 = __float2bfloat16(e3);
                CVT2(Pa_h[j][2 * h], e0, e1);
                CVT2(Pa_h[j][2 * h + 1], e2, e3);
                CVT2(Pa_l[j][2 * h], e0 - __bfloat162float(c0), e1 - __bfloat162float(c1));
                CVT2(Pa_l[j][2 * h + 1], e2 - __bfloat162float(c2), e3 - __bfloat162float(c3));
            }
        }

        // ---- O += P G^T (warp: q16 x all 128 i), 3-term ----
        #pragma unroll
        for (int j = 0; j < 4; j++) {
            #pragma unroll
            for (int np = 0; np < 8; np++) {
                uint32_t gb = st + 34816 + (uint32_t)((16 * np + brow) * 144 + 32 * j + bcol);
                uint32_t gh[4], gl[4];
                LDSM4(gh[0], gh[1], gh[2], gh[3], gb);
                LDSM4(gl[0], gl[1], gl[2], gl[3], gb + 18432);
                #pragma unroll
                for (int h = 0; h < 2; h++) {
                    mma_bf16(Ofr[2 * np + h], Pa_h[j][0], Pa_h[j][1], Pa_h[j][2], Pa_h[j][3],
                             gh[2 * h], gh[2 * h + 1]);
                    mma_bf16(Ofr[2 * np + h], Pa_h[j][0], Pa_h[j][1], Pa_h[j][2], Pa_h[j][3],
                             gl[2 * h], gl[2 * h + 1]);
                    mma_bf16(Ofr[2 * np + h], Pa_l[j][0], Pa_l[j][1], Pa_l[j][2], Pa_l[j][3],
                             gh[2 * h], gh[2 * h + 1]);
                }
            }
        }

        // ---- pipeline: prefetch kt+2 (stage last read at kt-1), wait kt+1 ----
        if (kt + 2 < NTOK / 64) {
            issue(kt + 2);
            CP_WAIT(1);          // FIFO: tile kt+1 group complete
        } else {
            CP_WAIT(0);          // drain tail
        }
        __syncthreads();         // kt+1 visible; also read-fence for this stage
    }

    // ---- l reduce (warp-local rows), normalize, write Os[i][q] fp32 ----
    ls0 += __shfl_xor_sync(0xffffffffu, ls0, 1);
    ls0 += __shfl_xor_sync(0xffffffffu, ls0, 2);
    ls1 += __shfl_xor_sync(0xffffffffu, ls1, 1);
    ls1 += __shfl_xor_sync(0xffffffffu, ls1, 2);
    float inv0 = 1.f / ls0, inv1 = 1.f / ls1;

    float* Os = (float*)(smc + O_OS);   // [128 i][132]
    #pragma unroll
    for (int nt = 0; nt < 16; nt++)
        #pragma unroll
        for (int j = 0; j < 4; j++) {
            int q = qw + lr + 8 * (j >> 1);
            int i = 8 * nt + 2 * lc + (j & 1);
            Os[i * 132 + q] = Ofr[nt][j] * ((j >> 1) ? inv1 : inv0);
        }
    float* Wt = (float*)(smc + O_WT);   // [128 i][260] = Ww^T
    #pragma unroll
    for (int j = 0; j < 32; j++) {
        int fl = tid + 256 * j, c = fl >> 5, i4 = (fl & 31) * 4;
        float4 v = *(const float4*)(Ww + (size_t)c * IC + i4);
        Wt[(i4 + 0) * 260 + c] = v.x; Wt[(i4 + 1) * 260 + c] = v.y;
        Wt[(i4 + 2) * 260 + c] = v.z; Wt[(i4 + 3) * 260 + c] = v.w;
    }
    __syncthreads();

    // ---- out[c][q] = Ww Os + b + x (fp32 SIMT) ----
    const int tx = tid & 15, ty = tid >> 4;
    for (int qh = 0; qh < 2; qh++) {
        float acc[16][4];
        #pragma unroll
        for (int cc = 0; cc < 16; cc++)
            acc[cc][0] = acc[cc][1] = acc[cc][2] = acc[cc][3] = 0.f;
        #pragma unroll 4
        for (int i = 0; i < 128; i++) {
            float4 ov = *(const float4*)(Os + i * 132 + qh * 64 + 4 * tx);
            #pragma unroll
            for (int cc = 0; cc < 16; cc++) {
                float w = Wt[i * 260 + ty + 16 * cc];
                acc[cc][0] += w * ov.x; acc[cc][1] += w * ov.y;
                acc[cc][2] += w * ov.z; acc[cc][3] += w * ov.w;
            }
        }
        #pragma unroll
        for (int cc = 0; cc < 16; cc++) {
            int c = ty + 16 * cc;
            float wb = Wb[c];
            size_t base = ((size_t)b * CH + c) * NTOK + q0 + qh * 64 + 4 * tx;
            float4 xr = *(const float4*)(x + base);
            float4 o;
            o.x = acc[cc][0] + wb + xr.x; o.y = acc[cc][1] + wb + xr.y;
            o.z = acc[cc][2] + wb + xr.z; o.w = acc[cc][3] + wb + xr.w;
            *(float4*)(out + base) = o;
        }
    }
}

// ---------------------------------------------------------------------------
extern "C" void kernel_launch(void* const* d_in, const int* in_sizes, int n_in,
                              void* d_out, int out_size)
{
    const float* x    = (const float*)d_in[0];
    const float* g_w  = (const float*)d_in[1];
    const float* g_b  = (const float*)d_in[2];
    const float* th_w = (const float*)d_in[3];
    const float* th_b = (const float*)d_in[4];
    const float* ph_w = (const float*)d_in[5];
    const float* ph_b = (const float*)d_in[6];
    const float* W_w  = (const float*)d_in[7];
    const float* W_b  = (const float*)d_in[8];
    float* out = (float*)d_out;

    cudaFuncSetAttribute(proj_kernel, cudaFuncAttributeMaxDynamicSharedMemorySize, SMEM_PROJ);
    cudaFuncSetAttribute(attn_kernel, cudaFuncAttributeMaxDynamicSharedMemorySize, SMEM_ATTN);

    convert_w<<<96, 256>>>(th_w, th_b, ph_w, ph_b, g_w, g_b);
    convert_x<<<dim3(256, BATCH), 256>>>(x);
    proj_kernel<<<dim3(NTOK / 64, BATCH), 256, SMEM_PROJ>>>();
    attn_kernel<<<dim3(NTOK / 128, BATCH), 256, SMEM_ATTN>>>(
        x, W_w, W_b, out);
}